// round 7
// baseline (speedup 1.0000x reference)
// R6: planar hi/lo pair precompute + 2-stage single-barrier pipelined mma GEMM.
// Attention (R5) and RoPE unchanged. Label: "gemm-pairs-2stage".
#include <cuda_runtime.h>
#include <cuda_bf16.h>
#include <cstdint>

// Problem constants (Qwen2 GQA): B=2, S=2048, D=3584, H=28, KV=4, HD=128
#define Bn    2
#define Sn    2048
#define Dn    3584
#define Hn    28
#define KVn   4
#define HDn   128
#define NREP  7
#define Mn    (Bn * Sn)          // 4096
#define KVD   (KVn * HDn)        // 512
#define SCALE 0.08838834764831845f

// fp32 scratch
__device__ float g_q[(size_t)Mn * Dn];
__device__ float g_k[(size_t)Mn * KVD];
__device__ float g_v[(size_t)Mn * KVD];
__device__ float g_attn[(size_t)Mn * Dn];
// planar (hi,lo) bf16 pair arrays
__device__ __nv_bfloat162 g_ap [(size_t)Mn  * Dn];   // x pairs, later attn pairs
__device__ __nv_bfloat162 g_wqp[(size_t)Dn  * Dn];
__device__ __nv_bfloat162 g_wkp[(size_t)KVD * Dn];
__device__ __nv_bfloat162 g_wvp[(size_t)KVD * Dn];
__device__ __nv_bfloat162 g_wop[(size_t)Dn  * Dn];

// ===========================================================================
// mma/ldsm helpers
// ===========================================================================
__device__ __forceinline__ void ldsm4(uint32_t& r0, uint32_t& r1,
                                      uint32_t& r2, uint32_t& r3, uint32_t addr)
{
    asm volatile("ldmatrix.sync.aligned.m8n8.x4.shared.b16 {%0,%1,%2,%3}, [%4];\n"
                 : "=r"(r0), "=r"(r1), "=r"(r2), "=r"(r3) : "r"(addr));
}

__device__ __forceinline__ void ldsm4t(uint32_t& r0, uint32_t& r1,
                                       uint32_t& r2, uint32_t& r3, uint32_t addr)
{
    asm volatile("ldmatrix.sync.aligned.m8n8.x4.trans.shared.b16 {%0,%1,%2,%3}, [%4];\n"
                 : "=r"(r0), "=r"(r1), "=r"(r2), "=r"(r3) : "r"(addr));
}

__device__ __forceinline__ void mma16816(float* c, const uint32_t* a,
                                         uint32_t b0, uint32_t b1)
{
    asm volatile(
        "mma.sync.aligned.m16n8k16.row.col.f32.bf16.bf16.f32 "
        "{%0,%1,%2,%3}, {%4,%5,%6,%7}, {%8,%9}, {%0,%1,%2,%3};\n"
        : "+f"(c[0]), "+f"(c[1]), "+f"(c[2]), "+f"(c[3])
        : "r"(a[0]), "r"(a[1]), "r"(a[2]), "r"(a[3]), "r"(b0), "r"(b1));
}

// ===========================================================================
// pack_hilo: fp32 -> planar (hi, lo) bf16 pairs. 4 elems/thread, streaming.
// ===========================================================================
__global__ void pack_hilo_kernel(const float* __restrict__ in,
                                 __nv_bfloat162* __restrict__ out, int total)
{
    int idx = (blockIdx.x * blockDim.x + threadIdx.x) << 2;
    if (idx >= total) return;
    float4 v = *(const float4*)(in + idx);
    float f[4] = {v.x, v.y, v.z, v.w};
    __nv_bfloat162 o[4];
#pragma unroll
    for (int i = 0; i < 4; ++i) {
        __nv_bfloat16 hi = __float2bfloat16(f[i]);
        __nv_bfloat16 lo = __float2bfloat16(f[i] - __bfloat162float(hi));
        o[i].x = hi; o[i].y = lo;
    }
    *(uint4*)(out + idx) = *(const uint4*)o;
}

// ===========================================================================
// Pair-fed bf16-split3 GEMM: C[M,N] = A[M,K]*W[N,K]^T (+bias), fp32 out.
// A, W given as planar (hi,lo) pairs. smem holds K-interleaved triplets:
// A -> (hi,hi,lo), W -> (hi,lo,hi); bf16 dot over 3K = hiA*hiW+hiA*loW+loA*hiW.
// Block 128x128, fp32 K-step 16 (=48 bf16 = 3 mma k-steps), 256 thr, 8 warps.
// 2-stage smem, ONE barrier per K-step:
//   iter k: sync; store tile k+1 -> buf[cur^1]; mma buf[cur].
// ===========================================================================
#define LDA 56                       // triplet row stride (bf16): 112B
#define OPST (128 * LDA)             // bf16 elems per operand-stage

// interleave 8 (hi,lo) pairs into 24-bf16 triplet run, store 48B.
template <int AMODE>
__device__ __forceinline__ void sts_trip(__nv_bfloat16* dst, uint4 p0, uint4 p1)
{
    uint32_t pw[8] = {p0.x, p0.y, p0.z, p0.w, p1.x, p1.y, p1.z, p1.w};
    __nv_bfloat16 t[24];
#pragma unroll
    for (int i = 0; i < 8; ++i) {
        __nv_bfloat162 pr = *(__nv_bfloat162*)&pw[i];
        if (AMODE) { t[3*i] = pr.x; t[3*i+1] = pr.x; t[3*i+2] = pr.y; }
        else       { t[3*i] = pr.x; t[3*i+1] = pr.y; t[3*i+2] = pr.x; }
    }
    uint2*       d = (uint2*)dst;
    const uint2* s = (const uint2*)t;
#pragma unroll
    for (int j = 0; j < 6; ++j) d[j] = s[j];
}

__global__ void __launch_bounds__(256) gemm_pairs_kernel(
    const __nv_bfloat162* __restrict__ A, const __nv_bfloat162* __restrict__ W,
    const float* __restrict__ bias, float* __restrict__ C, int N, int K)
{
    extern __shared__ __align__(16) __nv_bfloat16 smg[];
    // layout: [stage0 A][stage0 W][stage1 A][stage1 W]
    __nv_bfloat16* As0 = smg;
    __nv_bfloat16* Ws0 = smg + OPST;

    const int tid  = threadIdx.x;
    const int lane = tid & 31, wid = tid >> 5;
    const int m0 = blockIdx.y << 7, n0 = blockIdx.x << 7;
    const int wm = (wid & 3) << 5;
    const int wn = (wid >> 2) << 6;

    // producer mapping: row 0..127, fp32-col offset 0 or 8
    const int pr = tid >> 1;
    const int pc = (tid & 1) << 3;
    const __nv_bfloat162* Ag = A + (size_t)(m0 + pr) * K + pc;
    const __nv_bfloat162* Wg = W + (size_t)(n0 + pr) * K + pc;
    const int soff = pr * LDA + pc * 3;

    // ldmatrix lane->address components (validated mapping)
    const int a_row  = wm + (lane & 15);
    const int a_coff = (lane >> 4) << 3;
    const int b_row  = wn + ((lane >> 4) << 3) + (lane & 7);
    const int b_coff = ((lane >> 3) & 1) << 3;
    const uint32_t s_base = (uint32_t)__cvta_generic_to_shared(smg);

    float acc[2][8][4];
#pragma unroll
    for (int i = 0; i < 2; ++i)
#pragma unroll
        for (int j = 0; j < 8; ++j)
#pragma unroll
            for (int e = 0; e < 4; ++e) acc[i][j][e] = 0.f;

    // prologue: tile 0 -> stage 0; prefetch tile 1 into regs
    uint4 ra0 = *(const uint4*)(Ag),     ra1 = *(const uint4*)(Ag + 4);
    uint4 rw0 = *(const uint4*)(Wg),     rw1 = *(const uint4*)(Wg + 4);
    sts_trip<1>(As0 + soff, ra0, ra1);
    sts_trip<0>(Ws0 + soff, rw0, rw1);
    if (16 < K) {
        ra0 = *(const uint4*)(Ag + 16);  ra1 = *(const uint4*)(Ag + 20);
        rw0 = *(const uint4*)(Wg + 16);  rw1 = *(const uint4*)(Wg + 20);
    }

    int cur = 0;
    for (int k0 = 0; k0 < K; k0 += 16) {
        __syncthreads();   // stores to buf[cur] visible; reads of buf[cur^1] done

        if (k0 + 16 < K) { // store tile k0+16 into the other stage
            const int nst = (cur ^ 1) * 2 * OPST;
            sts_trip<1>(smg + nst + soff, ra0, ra1);
            sts_trip<0>(smg + nst + OPST + soff, rw0, rw1);
            if (k0 + 32 < K) {   // prefetch tile k0+32
                ra0 = *(const uint4*)(Ag + k0 + 32);
                ra1 = *(const uint4*)(Ag + k0 + 36);
                rw0 = *(const uint4*)(Wg + k0 + 32);
                rw1 = *(const uint4*)(Wg + k0 + 36);
            }
        }

        const uint32_t as_b = s_base + (uint32_t)(cur * 2 * OPST * 2);
        const uint32_t ws_b = as_b + (uint32_t)(OPST * 2);
#pragma unroll
        for (int ks = 0; ks < 3; ++ks) {
            const int kk = ks << 4;
            uint32_t afr[2][4];
#pragma unroll
            for (int mi = 0; mi < 2; ++mi)
                ldsm4(afr[mi][0], afr[mi][1], afr[mi][2], afr[mi][3],
                      as_b + (uint32_t)(((a_row + mi * 16) * LDA + kk + a_coff) * 2));
            uint32_t bfr[4][4];
#pragma unroll
            for (int nq = 0; nq < 4; ++nq)
                ldsm4(bfr[nq][0], bfr[nq][1], bfr[nq][2], bfr[nq][3],
                      ws_b + (uint32_t)(((b_row + nq * 16) * LDA + kk + b_coff) * 2));
#pragma unroll
            for (int mi = 0; mi < 2; ++mi)
#pragma unroll
                for (int nq = 0; nq < 4; ++nq) {
                    mma16816(acc[mi][nq * 2 + 0], afr[mi], bfr[nq][0], bfr[nq][1]);
                    mma16816(acc[mi][nq * 2 + 1], afr[mi], bfr[nq][2], bfr[nq][3]);
                }
        }
        cur ^= 1;
    }

    const int g = lane >> 2, t = lane & 3;
#pragma unroll
    for (int mi = 0; mi < 2; ++mi)
#pragma unroll
        for (int ni = 0; ni < 8; ++ni) {
            int row = m0 + wm + mi * 16 + g;
            int col = n0 + wn + ni * 8 + t * 2;
            float b0 = bias ? bias[col]     : 0.f;
            float b1 = bias ? bias[col + 1] : 0.f;
            C[(size_t)row * N + col]           = acc[mi][ni][0] + b0;
            C[(size_t)row * N + col + 1]       = acc[mi][ni][1] + b1;
            C[(size_t)(row + 8) * N + col]     = acc[mi][ni][2] + b0;
            C[(size_t)(row + 8) * N + col + 1] = acc[mi][ni][3] + b1;
        }
}
#define GEMM_SMEM (4 * OPST * 2)   // 57344 bytes

// ===========================================================================
// RoPE (unchanged)
// ===========================================================================
__global__ void rope_kernel(const float* __restrict__ cosT,
                            const float* __restrict__ sinT)
{
    const int QP = Mn * Hn * 64;
    const int TP = QP + Mn * KVn * 64;
    int idx = blockIdx.x * blockDim.x + threadIdx.x;
    if (idx >= TP) return;

    float* ptr;
    int s, p;
    if (idx < QP) {
        p = idx & 63;
        int hh = (idx >> 6) % Hn;
        int bs = idx / (64 * Hn);
        s = bs & (Sn - 1);
        ptr = g_q + (size_t)bs * Dn + hh * HDn + 2 * p;
    } else {
        int t = idx - QP;
        p = t & 63;
        int kv = (t >> 6) & 3;
        int bs = t >> 8;
        s = bs & (Sn - 1);
        ptr = g_k + (size_t)bs * KVD + kv * HDn + 2 * p;
    }
    float c  = cosT[s * 64 + p];
    float sn = sinT[s * 64 + p];
    float xr = ptr[0], xi = ptr[1];
    ptr[0] = xr * c - xi * sn;
    ptr[1] = xr * sn + xi * c;
}

// ===========================================================================
// Tensor-core flash attention (unchanged from R5, verified @4286us)
// ===========================================================================
#define LQA 136
#define LPV 72
#define ATTN_SMEM ((2 * 128 * LQA + 4 * 64 * LQA + 2 * 128 * LPV) * 2)

__device__ __forceinline__ void cvt4hl(__nv_bfloat16* dhi, __nv_bfloat16* dlo, float4 v)
{
    float f[4] = {v.x, v.y, v.z, v.w};
    __nv_bfloat16 h[4], l[4];
#pragma unroll
    for (int i = 0; i < 4; ++i) {
        h[i] = __float2bfloat16(f[i]);
        l[i] = __float2bfloat16(f[i] - __bfloat162float(h[i]));
    }
    *(uint2*)dhi = *(const uint2*)h;
    *(uint2*)dlo = *(const uint2*)l;
}

__global__ void __launch_bounds__(256) attn_tc_kernel()
{
    extern __shared__ __align__(16) __nv_bfloat16 smb[];
    __nv_bfloat16* Qhi = smb;
    __nv_bfloat16* Qlo = Qhi + 128 * LQA;
    __nv_bfloat16* Khi = Qlo + 128 * LQA;
    __nv_bfloat16* Klo = Khi + 64 * LQA;
    __nv_bfloat16* Vhi = Klo + 64 * LQA;
    __nv_bfloat16* Vlo = Vhi + 64 * LQA;
    __nv_bfloat16* Phi = Vlo + 64 * LQA;
    __nv_bfloat16* Plo = Phi + 128 * LPV;

    const int qt = blockIdx.x, h = blockIdx.y, b = blockIdx.z;
    const int kvh = h / NREP;
    const int tid = threadIdx.x;
    const int lane = tid & 31, w = tid >> 5;
    const int qi0 = qt << 7;

    {
        const float* qg = g_q + (size_t)(b * Sn + qi0) * Dn + h * HDn;
        int r = tid >> 1, c0 = (tid & 1) << 6;
#pragma unroll
        for (int c = 0; c < 64; c += 4) {
            float4 v = *(const float4*)(qg + (size_t)r * Dn + c0 + c);
            cvt4hl(Qhi + r * LQA + c0 + c, Qlo + r * LQA + c0 + c, v);
        }
    }

    const int a_row_l = lane & 15;
    const int a_coff  = (lane >> 4) << 3;
    const int b_row_l = ((lane >> 4) << 3) + (lane & 7);
    const int b_coff  = ((lane >> 3) & 1) << 3;
    const int t_row = (((lane >> 3) & 1) << 3) + (lane & 7);
    const int t_col = (lane >> 4) << 3;

    const uint32_t qhi_b = (uint32_t)__cvta_generic_to_shared(Qhi);
    const uint32_t qlo_b = (uint32_t)__cvta_generic_to_shared(Qlo);
    const uint32_t khi_b = (uint32_t)__cvta_generic_to_shared(Khi);
    const uint32_t klo_b = (uint32_t)__cvta_generic_to_shared(Klo);
    const uint32_t vhi_b = (uint32_t)__cvta_generic_to_shared(Vhi);
    const uint32_t vlo_b = (uint32_t)__cvta_generic_to_shared(Vlo);
    const uint32_t phi_b = (uint32_t)__cvta_generic_to_shared(Phi);
    const uint32_t plo_b = (uint32_t)__cvta_generic_to_shared(Plo);

    const int g  = lane >> 2;
    const int t4 = lane & 3;
    const int qglob0 = qi0 + w * 16 + g;
    const int qglob1 = qglob0 + 8;

    float oacc[16][4];
#pragma unroll
    for (int i = 0; i < 16; ++i)
#pragma unroll
        for (int e = 0; e < 4; ++e) oacc[i][e] = 0.f;
    float m0 = -1e30f, m1 = -1e30f, l0 = 0.f, l1 = 0.f;

    const float* kg_base = g_k + (size_t)(b * Sn) * KVD + kvh * HDn;
    const float* vg_base = g_v + (size_t)(b * Sn) * KVD + kvh * HDn;

    const int jmax = qi0 + 64;
    for (int j0 = 0; j0 <= jmax; j0 += 64) {
        __syncthreads();
        {
            int r = tid >> 2, c0 = (tid & 3) << 5;
            const float* kg = kg_base + (size_t)(j0 + r) * KVD + c0;
            const float* vg = vg_base + (size_t)(j0 + r) * KVD + c0;
#pragma unroll
            for (int c = 0; c < 32; c += 4) {
                cvt4hl(Khi + r * LQA + c0 + c, Klo + r * LQA + c0 + c,
                       *(const float4*)(kg + c));
                cvt4hl(Vhi + r * LQA + c0 + c, Vlo + r * LQA + c0 + c,
                       *(const float4*)(vg + c));
            }
        }
        __syncthreads();

        float sacc[8][4];
#pragma unroll
        for (int i = 0; i < 8; ++i)
#pragma unroll
            for (int e = 0; e < 4; ++e) sacc[i][e] = 0.f;

#pragma unroll
        for (int pass = 0; pass < 3; ++pass) {
            const uint32_t ab = (pass == 2) ? qlo_b : qhi_b;
            const uint32_t bb = (pass == 1) ? klo_b : khi_b;
#pragma unroll
            for (int ks = 0; ks < 8; ++ks) {
                const int kk = ks << 4;
                uint32_t afr[4];
                ldsm4(afr[0], afr[1], afr[2], afr[3],
                      ab + (uint32_t)(((w * 16 + a_row_l) * LQA + kk + a_coff) * 2));
                uint32_t bfr[4][4];
#pragma unroll
                for (int nq = 0; nq < 4; ++nq)
                    ldsm4(bfr[nq][0], bfr[nq][1], bfr[nq][2], bfr[nq][3],
                          bb + (uint32_t)(((nq * 16 + b_row_l) * LQA + kk + b_coff) * 2));
#pragma unroll
                for (int nq = 0; nq < 4; ++nq) {
                    mma16816(sacc[nq * 2 + 0], afr, bfr[nq][0], bfr[nq][1]);
                    mma16816(sacc[nq * 2 + 1], afr, bfr[nq][2], bfr[nq][3]);
                }
            }
        }

#pragma unroll
        for (int nq = 0; nq < 8; ++nq) {
            int cb = j0 + nq * 8 + t4 * 2;
            float s0 = sacc[nq][0] * SCALE;
            float s1 = sacc[nq][1] * SCALE;
            float s2 = sacc[nq][2] * SCALE;
            float s3 = sacc[nq][3] * SCALE;
            if (cb     > qglob0) s0 = -1e30f;
            if (cb + 1 > qglob0) s1 = -1e30f;
            if (cb     > qglob1) s2 = -1e30f;
            if (cb + 1 > qglob1) s3 = -1e30f;
            sacc[nq][0] = s0; sacc[nq][1] = s1;
            sacc[nq][2] = s2; sacc[nq][3] = s3;
        }

        float rm0 = -1e30f, rm1 = -1e30f;
#pragma unroll
        for (int nq = 0; nq < 8; ++nq) {
            rm0 = fmaxf(rm0, fmaxf(sacc[nq][0], sacc[nq][1]));
            rm1 = fmaxf(rm1, fmaxf(sacc[nq][2], sacc[nq][3]));
        }
        rm0 = fmaxf(rm0, __shfl_xor_sync(0xffffffffu, rm0, 1));
        rm0 = fmaxf(rm0, __shfl_xor_sync(0xffffffffu, rm0, 2));
        rm1 = fmaxf(rm1, __shfl_xor_sync(0xffffffffu, rm1, 1));
        rm1 = fmaxf(rm1, __shfl_xor_sync(0xffffffffu, rm1, 2));
        float mn0 = fmaxf(m0, rm0), mn1 = fmaxf(m1, rm1);
        float al0 = __expf(m0 - mn0), al1 = __expf(m1 - mn1);

        __syncwarp();
        float rs0 = 0.f, rs1 = 0.f;
        const int prow0 = w * 16 + g;
#pragma unroll
        for (int nq = 0; nq < 8; ++nq) {
            int col = nq * 8 + t4 * 2;
            float p0 = __expf(sacc[nq][0] - mn0);
            float p1 = __expf(sacc[nq][1] - mn0);
            float p2 = __expf(sacc[nq][2] - mn1);
            float p3 = __expf(sacc[nq][3] - mn1);
            rs0 += p0 + p1;  rs1 += p2 + p3;
            __nv_bfloat162 h01, l01, h23, l23;
            h01.x = __float2bfloat16(p0);
            h01.y = __float2bfloat16(p1);
            l01.x = __float2bfloat16(p0 - __bfloat162float(h01.x));
            l01.y = __float2bfloat16(p1 - __bfloat162float(h01.y));
            h23.x = __float2bfloat16(p2);
            h23.y = __float2bfloat16(p3);
            l23.x = __float2bfloat16(p2 - __bfloat162float(h23.x));
            l23.y = __float2bfloat16(p3 - __bfloat162float(h23.y));
            *(__nv_bfloat162*)(Phi + prow0 * LPV + col)       = h01;
            *(__nv_bfloat162*)(Plo + prow0 * LPV + col)       = l01;
            *(__nv_bfloat162*)(Phi + (prow0 + 8) * LPV + col) = h23;
            *(__nv_bfloat162*)(Plo + (prow0 + 8) * LPV + col) = l23;
        }
        rs0 += __shfl_xor_sync(0xffffffffu, rs0, 1);
        rs0 += __shfl_xor_sync(0xffffffffu, rs0, 2);
        rs1 += __shfl_xor_sync(0xffffffffu, rs1, 1);
        rs1 += __shfl_xor_sync(0xffffffffu, rs1, 2);
        l0 = l0 * al0 + rs0;  l1 = l1 * al1 + rs1;
        m0 = mn0;  m1 = mn1;
#pragma unroll
        for (int nn = 0; nn < 16; ++nn) {
            oacc[nn][0] *= al0; oacc[nn][1] *= al0;
            oacc[nn][2] *= al1; oacc[nn][3] *= al1;
        }
        __syncwarp();

#pragma unroll
        for (int pass = 0; pass < 3; ++pass) {
            const uint32_t ab = (pass == 2) ? plo_b : phi_b;
            const uint32_t bb = (pass == 1) ? vlo_b : vhi_b;
#pragma unroll
            for (int ks = 0; ks < 4; ++ks) {
                const int kk = ks << 4;
                uint32_t afr[4];
                ldsm4(afr[0], afr[1], afr[2], afr[3],
                      ab + (uint32_t)(((w * 16 + a_row_l) * LPV + kk + a_coff) * 2));
#pragma unroll
                for (int nh = 0; nh < 8; ++nh) {
                    uint32_t b0, b1, b2, b3;
                    ldsm4t(b0, b1, b2, b3,
                           bb + (uint32_t)(((kk + t_row) * LQA + nh * 16 + t_col) * 2));
                    mma16816(oacc[nh * 2 + 0], afr, b0, b1);
                    mma16816(oacc[nh * 2 + 1], afr, b2, b3);
                }
            }
        }
    }

    float inv0 = 1.f / l0, inv1 = 1.f / l1;
    float* ob0 = g_attn + (size_t)(b * Sn + qglob0) * Dn + h * HDn;
    float* ob1 = g_attn + (size_t)(b * Sn + qglob1) * Dn + h * HDn;
#pragma unroll
    for (int nn = 0; nn < 16; ++nn) {
        int col = nn * 8 + t4 * 2;
        float2 v0 = {oacc[nn][0] * inv0, oacc[nn][1] * inv0};
        float2 v1 = {oacc[nn][2] * inv1, oacc[nn][3] * inv1};
        *(float2*)(ob0 + col) = v0;
        *(float2*)(ob1 + col) = v1;
    }
}

// ===========================================================================
// Launch
// ===========================================================================
extern "C" void kernel_launch(void* const* d_in, const int* in_sizes, int n_in,
                              void* d_out, int out_size)
{
    const float* x    = (const float*)d_in[0];
    const float* wq_w = (const float*)d_in[1];
    const float* wq_b = (const float*)d_in[2];
    const float* wk_w = (const float*)d_in[3];
    const float* wk_b = (const float*)d_in[4];
    const float* wv_w = (const float*)d_in[5];
    const float* wv_b = (const float*)d_in[6];
    const float* wo_w = (const float*)d_in[7];
    const float* fcos = (const float*)d_in[10];
    const float* fsin = (const float*)d_in[11];
    float* out = (float*)d_out;

    float *q_p, *k_p, *v_p, *attn_p;
    __nv_bfloat162 *ap, *wqp, *wkp, *wvp, *wop;
    cudaGetSymbolAddress((void**)&q_p,    g_q);
    cudaGetSymbolAddress((void**)&k_p,    g_k);
    cudaGetSymbolAddress((void**)&v_p,    g_v);
    cudaGetSymbolAddress((void**)&attn_p, g_attn);
    cudaGetSymbolAddress((void**)&ap,  g_ap);
    cudaGetSymbolAddress((void**)&wqp, g_wqp);
    cudaGetSymbolAddress((void**)&wkp, g_wkp);
    cudaGetSymbolAddress((void**)&wvp, g_wvp);
    cudaGetSymbolAddress((void**)&wop, g_wop);

    const int TPB = 256;
    auto cdiv = [](int a, int b) { return (a + b - 1) / b; };

    // pack fp32 -> (hi,lo) pairs
    pack_hilo_kernel<<<cdiv(Mn * Dn / 4,  TPB), TPB>>>(x,    ap,  Mn * Dn);
    pack_hilo_kernel<<<cdiv(Dn * Dn / 4,  TPB), TPB>>>(wq_w, wqp, Dn * Dn);
    pack_hilo_kernel<<<cdiv(KVD * Dn / 4, TPB), TPB>>>(wk_w, wkp, KVD * Dn);
    pack_hilo_kernel<<<cdiv(KVD * Dn / 4, TPB), TPB>>>(wv_w, wvp, KVD * Dn);
    pack_hilo_kernel<<<cdiv(Dn * Dn / 4,  TPB), TPB>>>(wo_w, wop, Dn * Dn);

    cudaFuncSetAttribute(gemm_pairs_kernel,
                         cudaFuncAttributeMaxDynamicSharedMemorySize, GEMM_SMEM);

    // QKV projections
    gemm_pairs_kernel<<<dim3(Dn / 128,  Mn / 128), TPB, GEMM_SMEM>>>(ap, wqp, wq_b, q_p, Dn,  Dn);
    gemm_pairs_kernel<<<dim3(KVD / 128, Mn / 128), TPB, GEMM_SMEM>>>(ap, wkp, wk_b, k_p, KVD, Dn);
    gemm_pairs_kernel<<<dim3(KVD / 128, Mn / 128), TPB, GEMM_SMEM>>>(ap, wvp, wv_b, v_p, KVD, Dn);

    // RoPE
    int nrope = Mn * Hn * 64 + Mn * KVn * 64;
    rope_kernel<<<cdiv(nrope, TPB), TPB>>>(fcos, fsin);

    // Flash attention (tensor cores)
    cudaFuncSetAttribute(attn_tc_kernel, cudaFuncAttributeMaxDynamicSharedMemorySize,
                         ATTN_SMEM);
    attn_tc_kernel<<<dim3(Sn / 128, Hn, Bn), TPB, ATTN_SMEM>>>();

    // O projection: pack attn (reuse ap), GEMM into d_out
    pack_hilo_kernel<<<cdiv(Mn * Dn / 4, TPB), TPB>>>(attn_p, ap, Mn * Dn);
    gemm_pairs_kernel<<<dim3(Dn / 128, Mn / 128), TPB, GEMM_SMEM>>>(ap, wop, nullptr, out, Dn, Dn);
}

// round 9
// speedup vs baseline: 1.0802x; 1.0802x over previous
// R8: merged QKV GEMM (one 4608-wide launch, kills KV wave waste) + RoPE fused
// into GEMM epilogue. tcgen05 is OFF the table (harness targets sm_100 non-a).
// GEMM mainloop = R6 verified; attention = R5 verified. Label: "qkv-merge-rope-fuse".
#include <cuda_runtime.h>
#include <cuda_bf16.h>
#include <cstdint>

// Problem constants (Qwen2 GQA): B=2, S=2048, D=3584, H=28, KV=4, HD=128
#define Bn    2
#define Sn    2048
#define Dn    3584
#define Hn    28
#define KVn   4
#define HDn   128
#define NREP  7
#define Mn    (Bn * Sn)          // 4096
#define KVD   (KVn * HDn)        // 512
#define NQKV  (Dn + 2 * KVD)     // 4608 merged output width
#define SCALE 0.08838834764831845f

// fp32 scratch
__device__ float g_q[(size_t)Mn * Dn];
__device__ float g_k[(size_t)Mn * KVD];
__device__ float g_v[(size_t)Mn * KVD];
__device__ float g_attn[(size_t)Mn * Dn];
// planar (hi,lo) bf16 pair arrays
__device__ __nv_bfloat162 g_ap   [(size_t)Mn   * Dn];   // x pairs, later attn pairs
__device__ __nv_bfloat162 g_wqkvp[(size_t)NQKV * Dn];   // wq|wk|wv stacked rows
__device__ __nv_bfloat162 g_wop  [(size_t)Dn   * Dn];

// ===========================================================================
// mma/ldsm helpers
// ===========================================================================
__device__ __forceinline__ void ldsm4(uint32_t& r0, uint32_t& r1,
                                      uint32_t& r2, uint32_t& r3, uint32_t addr)
{
    asm volatile("ldmatrix.sync.aligned.m8n8.x4.shared.b16 {%0,%1,%2,%3}, [%4];\n"
                 : "=r"(r0), "=r"(r1), "=r"(r2), "=r"(r3) : "r"(addr));
}

__device__ __forceinline__ void ldsm4t(uint32_t& r0, uint32_t& r1,
                                       uint32_t& r2, uint32_t& r3, uint32_t addr)
{
    asm volatile("ldmatrix.sync.aligned.m8n8.x4.trans.shared.b16 {%0,%1,%2,%3}, [%4];\n"
                 : "=r"(r0), "=r"(r1), "=r"(r2), "=r"(r3) : "r"(addr));
}

__device__ __forceinline__ void mma16816(float* c, const uint32_t* a,
                                         uint32_t b0, uint32_t b1)
{
    asm volatile(
        "mma.sync.aligned.m16n8k16.row.col.f32.bf16.bf16.f32 "
        "{%0,%1,%2,%3}, {%4,%5,%6,%7}, {%8,%9}, {%0,%1,%2,%3};\n"
        : "+f"(c[0]), "+f"(c[1]), "+f"(c[2]), "+f"(c[3])
        : "r"(a[0]), "r"(a[1]), "r"(a[2]), "r"(a[3]), "r"(b0), "r"(b1));
}

// ===========================================================================
// pack_hilo: fp32 -> planar (hi, lo) bf16 pairs (verified)
// ===========================================================================
__global__ void pack_hilo_kernel(const float* __restrict__ in,
                                 __nv_bfloat162* __restrict__ out, int total)
{
    int idx = (blockIdx.x * blockDim.x + threadIdx.x) << 2;
    if (idx >= total) return;
    float4 v = *(const float4*)(in + idx);
    float f[4] = {v.x, v.y, v.z, v.w};
    __nv_bfloat162 o[4];
#pragma unroll
    for (int i = 0; i < 4; ++i) {
        __nv_bfloat16 hi = __float2bfloat16(f[i]);
        __nv_bfloat16 lo = __float2bfloat16(f[i] - __bfloat162float(hi));
        o[i].x = hi; o[i].y = lo;
    }
    *(uint4*)(out + idx) = *(const uint4*)o;
}

// ===========================================================================
// Pair-fed bf16-split3 GEMM with region-dispatch epilogue + optional RoPE.
// Mainloop identical to R6 (verified). Output columns route to:
//   col < 3584          -> qd (stride Dn)
//   3584 <= col < 4096  -> kd (stride KVD), local col - 3584
//   col >= 4096         -> vd (stride KVD), local col - 4096
// RoPE applied (fp32, same math as rope_kernel) to cols < rope_n.
// ===========================================================================
#define LDA 56
#define OPST (128 * LDA)
#define GEMM_SMEM (4 * OPST * 2)   // 57344 bytes

template <int AMODE>
__device__ __forceinline__ void sts_trip(__nv_bfloat16* dst, uint4 p0, uint4 p1)
{
    uint32_t pw[8] = {p0.x, p0.y, p0.z, p0.w, p1.x, p1.y, p1.z, p1.w};
    __nv_bfloat16 t[24];
#pragma unroll
    for (int i = 0; i < 8; ++i) {
        __nv_bfloat162 pr = *(__nv_bfloat162*)&pw[i];
        if (AMODE) { t[3*i] = pr.x; t[3*i+1] = pr.x; t[3*i+2] = pr.y; }
        else       { t[3*i] = pr.x; t[3*i+1] = pr.y; t[3*i+2] = pr.x; }
    }
    uint2*       d = (uint2*)dst;
    const uint2* s = (const uint2*)t;
#pragma unroll
    for (int j = 0; j < 6; ++j) d[j] = s[j];
}

__global__ void __launch_bounds__(256) gemm_pairs_kernel(
    const __nv_bfloat162* __restrict__ A, const __nv_bfloat162* __restrict__ W,
    const float* __restrict__ bq, const float* __restrict__ bk,
    const float* __restrict__ bv,
    float* __restrict__ qd, float* __restrict__ kd, float* __restrict__ vd,
    int K, int rope_n,
    const float* __restrict__ cosT, const float* __restrict__ sinT)
{
    extern __shared__ __align__(16) __nv_bfloat16 smg[];
    __nv_bfloat16* As0 = smg;
    __nv_bfloat16* Ws0 = smg + OPST;

    const int tid  = threadIdx.x;
    const int lane = tid & 31, wid = tid >> 5;
    const int m0 = blockIdx.y << 7, n0 = blockIdx.x << 7;
    const int wm = (wid & 3) << 5;
    const int wn = (wid >> 2) << 6;

    const int pr = tid >> 1;
    const int pc = (tid & 1) << 3;
    const __nv_bfloat162* Ag = A + (size_t)(m0 + pr) * K + pc;
    const __nv_bfloat162* Wg = W + (size_t)(n0 + pr) * K + pc;
    const int soff = pr * LDA + pc * 3;

    const int a_row  = wm + (lane & 15);
    const int a_coff = (lane >> 4) << 3;
    const int b_row  = wn + ((lane >> 4) << 3) + (lane & 7);
    const int b_coff = ((lane >> 3) & 1) << 3;
    const uint32_t s_base = (uint32_t)__cvta_generic_to_shared(smg);

    float acc[2][8][4];
#pragma unroll
    for (int i = 0; i < 2; ++i)
#pragma unroll
        for (int j = 0; j < 8; ++j)
#pragma unroll
            for (int e = 0; e < 4; ++e) acc[i][j][e] = 0.f;

    uint4 ra0 = *(const uint4*)(Ag),     ra1 = *(const uint4*)(Ag + 4);
    uint4 rw0 = *(const uint4*)(Wg),     rw1 = *(const uint4*)(Wg + 4);
    sts_trip<1>(As0 + soff, ra0, ra1);
    sts_trip<0>(Ws0 + soff, rw0, rw1);
    if (16 < K) {
        ra0 = *(const uint4*)(Ag + 16);  ra1 = *(const uint4*)(Ag + 20);
        rw0 = *(const uint4*)(Wg + 16);  rw1 = *(const uint4*)(Wg + 20);
    }

    int cur = 0;
    for (int k0 = 0; k0 < K; k0 += 16) {
        __syncthreads();

        if (k0 + 16 < K) {
            const int nst = (cur ^ 1) * 2 * OPST;
            sts_trip<1>(smg + nst + soff, ra0, ra1);
            sts_trip<0>(smg + nst + OPST + soff, rw0, rw1);
            if (k0 + 32 < K) {
                ra0 = *(const uint4*)(Ag + k0 + 32);
                ra1 = *(const uint4*)(Ag + k0 + 36);
                rw0 = *(const uint4*)(Wg + k0 + 32);
                rw1 = *(const uint4*)(Wg + k0 + 36);
            }
        }

        const uint32_t as_b = s_base + (uint32_t)(cur * 2 * OPST * 2);
        const uint32_t ws_b = as_b + (uint32_t)(OPST * 2);
#pragma unroll
        for (int ks = 0; ks < 3; ++ks) {
            const int kk = ks << 4;
            uint32_t afr[2][4];
#pragma unroll
            for (int mi = 0; mi < 2; ++mi)
                ldsm4(afr[mi][0], afr[mi][1], afr[mi][2], afr[mi][3],
                      as_b + (uint32_t)(((a_row + mi * 16) * LDA + kk + a_coff) * 2));
            uint32_t bfr[4][4];
#pragma unroll
            for (int nq = 0; nq < 4; ++nq)
                ldsm4(bfr[nq][0], bfr[nq][1], bfr[nq][2], bfr[nq][3],
                      ws_b + (uint32_t)(((b_row + nq * 16) * LDA + kk + b_coff) * 2));
#pragma unroll
            for (int mi = 0; mi < 2; ++mi)
#pragma unroll
                for (int nq = 0; nq < 4; ++nq) {
                    mma16816(acc[mi][nq * 2 + 0], afr[mi], bfr[nq][0], bfr[nq][1]);
                    mma16816(acc[mi][nq * 2 + 1], afr[mi], bfr[nq][2], bfr[nq][3]);
                }
        }
        cur ^= 1;
    }

    // ---- epilogue: region dispatch + bias + optional RoPE ----
    const int g = lane >> 2, t = lane & 3;
#pragma unroll
    for (int mi = 0; mi < 2; ++mi) {
        const int row0 = m0 + wm + mi * 16 + g;
        const int row1 = row0 + 8;
        const int s0 = row0 & (Sn - 1);
        const int s1 = row1 & (Sn - 1);
#pragma unroll
        for (int ni = 0; ni < 8; ++ni) {
            const int col0 = n0 + wn + ni * 8 + t * 2;   // even
            float* dst; int ccol, stride;
            float bb0 = 0.f, bb1 = 0.f;
            if (col0 < Dn) {
                dst = qd; ccol = col0; stride = Dn;
                if (bq) { bb0 = bq[col0]; bb1 = bq[col0 + 1]; }
            } else if (col0 < Dn + KVD) {
                dst = kd; ccol = col0 - Dn; stride = KVD;
                bb0 = bk[ccol]; bb1 = bk[ccol + 1];
            } else {
                dst = vd; ccol = col0 - Dn - KVD; stride = KVD;
                bb0 = bv[ccol]; bb1 = bv[ccol + 1];
            }
            float2 v0 = {acc[mi][ni][0] + bb0, acc[mi][ni][1] + bb1};
            float2 v1 = {acc[mi][ni][2] + bb0, acc[mi][ni][3] + bb1};
            if (col0 < rope_n) {
                const int p = (col0 & 127) >> 1;
                float c0 = cosT[s0 * 64 + p], sn0 = sinT[s0 * 64 + p];
                float c1 = cosT[s1 * 64 + p], sn1 = sinT[s1 * 64 + p];
                float2 r0 = {v0.x * c0 - v0.y * sn0, v0.x * sn0 + v0.y * c0};
                float2 r1 = {v1.x * c1 - v1.y * sn1, v1.x * sn1 + v1.y * c1};
                v0 = r0; v1 = r1;
            }
            *(float2*)(dst + (size_t)row0 * stride + ccol) = v0;
            *(float2*)(dst + (size_t)row1 * stride + ccol) = v1;
        }
    }
}

// ===========================================================================
// Tensor-core flash attention (unchanged from R5, verified)
// ===========================================================================
#define LQA 136
#define LPV 72
#define ATTN_SMEM ((2 * 128 * LQA + 4 * 64 * LQA + 2 * 128 * LPV) * 2)

__device__ __forceinline__ void cvt4hl(__nv_bfloat16* dhi, __nv_bfloat16* dlo, float4 v)
{
    float f[4] = {v.x, v.y, v.z, v.w};
    __nv_bfloat16 h[4], l[4];
#pragma unroll
    for (int i = 0; i < 4; ++i) {
        h[i] = __float2bfloat16(f[i]);
        l[i] = __float2bfloat16(f[i] - __bfloat162float(h[i]));
    }
    *(uint2*)dhi = *(const uint2*)h;
    *(uint2*)dlo = *(const uint2*)l;
}

__global__ void __launch_bounds__(256) attn_tc_kernel()
{
    extern __shared__ __align__(16) __nv_bfloat16 smb[];
    __nv_bfloat16* Qhi = smb;
    __nv_bfloat16* Qlo = Qhi + 128 * LQA;
    __nv_bfloat16* Khi = Qlo + 128 * LQA;
    __nv_bfloat16* Klo = Khi + 64 * LQA;
    __nv_bfloat16* Vhi = Klo + 64 * LQA;
    __nv_bfloat16* Vlo = Vhi + 64 * LQA;
    __nv_bfloat16* Phi = Vlo + 64 * LQA;
    __nv_bfloat16* Plo = Phi + 128 * LPV;

    const int qt = blockIdx.x, h = blockIdx.y, b = blockIdx.z;
    const int kvh = h / NREP;
    const int tid = threadIdx.x;
    const int lane = tid & 31, w = tid >> 5;
    const int qi0 = qt << 7;

    {
        const float* qg = g_q + (size_t)(b * Sn + qi0) * Dn + h * HDn;
        int r = tid >> 1, c0 = (tid & 1) << 6;
#pragma unroll
        for (int c = 0; c < 64; c += 4) {
            float4 v = *(const float4*)(qg + (size_t)r * Dn + c0 + c);
            cvt4hl(Qhi + r * LQA + c0 + c, Qlo + r * LQA + c0 + c, v);
        }
    }

    const int a_row_l = lane & 15;
    const int a_coff  = (lane >> 4) << 3;
    const int b_row_l = ((lane >> 4) << 3) + (lane & 7);
    const int b_coff  = ((lane >> 3) & 1) << 3;
    const int t_row = (((lane >> 3) & 1) << 3) + (lane & 7);
    const int t_col = (lane >> 4) << 3;

    const uint32_t qhi_b = (uint32_t)__cvta_generic_to_shared(Qhi);
    const uint32_t qlo_b = (uint32_t)__cvta_generic_to_shared(Qlo);
    const uint32_t khi_b = (uint32_t)__cvta_generic_to_shared(Khi);
    const uint32_t klo_b = (uint32_t)__cvta_generic_to_shared(Klo);
    const uint32_t vhi_b = (uint32_t)__cvta_generic_to_shared(Vhi);
    const uint32_t vlo_b = (uint32_t)__cvta_generic_to_shared(Vlo);
    const uint32_t phi_b = (uint32_t)__cvta_generic_to_shared(Phi);
    const uint32_t plo_b = (uint32_t)__cvta_generic_to_shared(Plo);

    const int g  = lane >> 2;
    const int t4 = lane & 3;
    const int qglob0 = qi0 + w * 16 + g;
    const int qglob1 = qglob0 + 8;

    float oacc[16][4];
#pragma unroll
    for (int i = 0; i < 16; ++i)
#pragma unroll
        for (int e = 0; e < 4; ++e) oacc[i][e] = 0.f;
    float m0 = -1e30f, m1 = -1e30f, l0 = 0.f, l1 = 0.f;

    const float* kg_base = g_k + (size_t)(b * Sn) * KVD + kvh * HDn;
    const float* vg_base = g_v + (size_t)(b * Sn) * KVD + kvh * HDn;

    const int jmax = qi0 + 64;
    for (int j0 = 0; j0 <= jmax; j0 += 64) {
        __syncthreads();
        {
            int r = tid >> 2, c0 = (tid & 3) << 5;
            const float* kg = kg_base + (size_t)(j0 + r) * KVD + c0;
            const float* vg = vg_base + (size_t)(j0 + r) * KVD + c0;
#pragma unroll
            for (int c = 0; c < 32; c += 4) {
                cvt4hl(Khi + r * LQA + c0 + c, Klo + r * LQA + c0 + c,
                       *(const float4*)(kg + c));
                cvt4hl(Vhi + r * LQA + c0 + c, Vlo + r * LQA + c0 + c,
                       *(const float4*)(vg + c));
            }
        }
        __syncthreads();

        float sacc[8][4];
#pragma unroll
        for (int i = 0; i < 8; ++i)
#pragma unroll
            for (int e = 0; e < 4; ++e) sacc[i][e] = 0.f;

#pragma unroll
        for (int pass = 0; pass < 3; ++pass) {
            const uint32_t ab = (pass == 2) ? qlo_b : qhi_b;
            const uint32_t bb = (pass == 1) ? klo_b : khi_b;
#pragma unroll
            for (int ks = 0; ks < 8; ++ks) {
                const int kk = ks << 4;
                uint32_t afr[4];
                ldsm4(afr[0], afr[1], afr[2], afr[3],
                      ab + (uint32_t)(((w * 16 + a_row_l) * LQA + kk + a_coff) * 2));
                uint32_t bfr[4][4];
#pragma unroll
                for (int nq = 0; nq < 4; ++nq)
                    ldsm4(bfr[nq][0], bfr[nq][1], bfr[nq][2], bfr[nq][3],
                          bb + (uint32_t)(((nq * 16 + b_row_l) * LQA + kk + b_coff) * 2));
#pragma unroll
                for (int nq = 0; nq < 4; ++nq) {
                    mma16816(sacc[nq * 2 + 0], afr, bfr[nq][0], bfr[nq][1]);
                    mma16816(sacc[nq * 2 + 1], afr, bfr[nq][2], bfr[nq][3]);
                }
            }
        }

#pragma unroll
        for (int nq = 0; nq < 8; ++nq) {
            int cb = j0 + nq * 8 + t4 * 2;
            float s0 = sacc[nq][0] * SCALE;
            float s1 = sacc[nq][1] * SCALE;
            float s2 = sacc[nq][2] * SCALE;
            float s3 = sacc[nq][3] * SCALE;
            if (cb     > qglob0) s0 = -1e30f;
            if (cb + 1 > qglob0) s1 = -1e30f;
            if (cb     > qglob1) s2 = -1e30f;
            if (cb + 1 > qglob1) s3 = -1e30f;
            sacc[nq][0] = s0; sacc[nq][1] = s1;
            sacc[nq][2] = s2; sacc[nq][3] = s3;
        }

        float rm0 = -1e30f, rm1 = -1e30f;
#pragma unroll
        for (int nq = 0; nq < 8; ++nq) {
            rm0 = fmaxf(rm0, fmaxf(sacc[nq][0], sacc[nq][1]));
            rm1 = fmaxf(rm1, fmaxf(sacc[nq][2], sacc[nq][3]));
        }
        rm0 = fmaxf(rm0, __shfl_xor_sync(0xffffffffu, rm0, 1));
        rm0 = fmaxf(rm0, __shfl_xor_sync(0xffffffffu, rm0, 2));
        rm1 = fmaxf(rm1, __shfl_xor_sync(0xffffffffu, rm1, 1));
        rm1 = fmaxf(rm1, __shfl_xor_sync(0xffffffffu, rm1, 2));
        float mn0 = fmaxf(m0, rm0), mn1 = fmaxf(m1, rm1);
        float al0 = __expf(m0 - mn0), al1 = __expf(m1 - mn1);

        __syncwarp();
        float rs0 = 0.f, rs1 = 0.f;
        const int prow0 = w * 16 + g;
#pragma unroll
        for (int nq = 0; nq < 8; ++nq) {
            int col = nq * 8 + t4 * 2;
            float p0 = __expf(sacc[nq][0] - mn0);
            float p1 = __expf(sacc[nq][1] - mn0);
            float p2 = __expf(sacc[nq][2] - mn1);
            float p3 = __expf(sacc[nq][3] - mn1);
            rs0 += p0 + p1;  rs1 += p2 + p3;
            __nv_bfloat162 h01, l01, h23, l23;
            h01.x = __float2bfloat16(p0);
            h01.y = __float2bfloat16(p1);
            l01.x = __float2bfloat16(p0 - __bfloat162float(h01.x));
            l01.y = __float2bfloat16(p1 - __bfloat162float(h01.y));
            h23.x = __float2bfloat16(p2);
            h23.y = __float2bfloat16(p3);
            l23.x = __float2bfloat16(p2 - __bfloat162float(h23.x));
            l23.y = __float2bfloat16(p3 - __bfloat162float(h23.y));
            *(__nv_bfloat162*)(Phi + prow0 * LPV + col)       = h01;
            *(__nv_bfloat162*)(Plo + prow0 * LPV + col)       = l01;
            *(__nv_bfloat162*)(Phi + (prow0 + 8) * LPV + col) = h23;
            *(__nv_bfloat162*)(Plo + (prow0 + 8) * LPV + col) = l23;
        }
        rs0 += __shfl_xor_sync(0xffffffffu, rs0, 1);
        rs0 += __shfl_xor_sync(0xffffffffu, rs0, 2);
        rs1 += __shfl_xor_sync(0xffffffffu, rs1, 1);
        rs1 += __shfl_xor_sync(0xffffffffu, rs1, 2);
        l0 = l0 * al0 + rs0;  l1 = l1 * al1 + rs1;
        m0 = mn0;  m1 = mn1;
#pragma unroll
        for (int nn = 0; nn < 16; ++nn) {
            oacc[nn][0] *= al0; oacc[nn][1] *= al0;
            oacc[nn][2] *= al1; oacc[nn][3] *= al1;
        }
        __syncwarp();

#pragma unroll
        for (int pass = 0; pass < 3; ++pass) {
            const uint32_t ab = (pass == 2) ? plo_b : phi_b;
            const uint32_t bb = (pass == 1) ? vlo_b : vhi_b;
#pragma unroll
            for (int ks = 0; ks < 4; ++ks) {
                const int kk = ks << 4;
                uint32_t afr[4];
                ldsm4(afr[0], afr[1], afr[2], afr[3],
                      ab + (uint32_t)(((w * 16 + a_row_l) * LPV + kk + a_coff) * 2));
#pragma unroll
                for (int nh = 0; nh < 8; ++nh) {
                    uint32_t b0, b1, b2, b3;
                    ldsm4t(b0, b1, b2, b3,
                           bb + (uint32_t)(((kk + t_row) * LQA + nh * 16 + t_col) * 2));
                    mma16816(oacc[nh * 2 + 0], afr, b0, b1);
                    mma16816(oacc[nh * 2 + 1], afr, b2, b3);
                }
            }
        }
    }

    float inv0 = 1.f / l0, inv1 = 1.f / l1;
    float* ob0 = g_attn + (size_t)(b * Sn + qglob0) * Dn + h * HDn;
    float* ob1 = g_attn + (size_t)(b * Sn + qglob1) * Dn + h * HDn;
#pragma unroll
    for (int nn = 0; nn < 16; ++nn) {
        int col = nn * 8 + t4 * 2;
        float2 v0 = {oacc[nn][0] * inv0, oacc[nn][1] * inv0};
        float2 v1 = {oacc[nn][2] * inv1, oacc[nn][3] * inv1};
        *(float2*)(ob0 + col) = v0;
        *(float2*)(ob1 + col) = v1;
    }
}

// ===========================================================================
// Launch
// ===========================================================================
extern "C" void kernel_launch(void* const* d_in, const int* in_sizes, int n_in,
                              void* d_out, int out_size)
{
    const float* x    = (const float*)d_in[0];
    const float* wq_w = (const float*)d_in[1];
    const float* wq_b = (const float*)d_in[2];
    const float* wk_w = (const float*)d_in[3];
    const float* wk_b = (const float*)d_in[4];
    const float* wv_w = (const float*)d_in[5];
    const float* wv_b = (const float*)d_in[6];
    const float* wo_w = (const float*)d_in[7];
    const float* fcos = (const float*)d_in[10];
    const float* fsin = (const float*)d_in[11];
    float* out = (float*)d_out;

    float *q_p, *k_p, *v_p, *attn_p;
    __nv_bfloat162 *ap, *wqkvp, *wop;
    cudaGetSymbolAddress((void**)&q_p,    g_q);
    cudaGetSymbolAddress((void**)&k_p,    g_k);
    cudaGetSymbolAddress((void**)&v_p,    g_v);
    cudaGetSymbolAddress((void**)&attn_p, g_attn);
    cudaGetSymbolAddress((void**)&ap,    g_ap);
    cudaGetSymbolAddress((void**)&wqkvp, g_wqkvp);
    cudaGetSymbolAddress((void**)&wop,   g_wop);

    const int TPB = 256;
    auto cdiv = [](int a, int b) { return (a + b - 1) / b; };

    // pack fp32 -> (hi,lo) pairs; wq|wk|wv stacked into one array
    pack_hilo_kernel<<<cdiv(Mn * Dn / 4,  TPB), TPB>>>(x,    ap, Mn * Dn);
    pack_hilo_kernel<<<cdiv(Dn * Dn / 4,  TPB), TPB>>>(wq_w, wqkvp, Dn * Dn);
    pack_hilo_kernel<<<cdiv(KVD * Dn / 4, TPB), TPB>>>(wk_w, wqkvp + (size_t)Dn * Dn, KVD * Dn);
    pack_hilo_kernel<<<cdiv(KVD * Dn / 4, TPB), TPB>>>(wv_w, wqkvp + (size_t)(Dn + KVD) * Dn, KVD * Dn);
    pack_hilo_kernel<<<cdiv(Dn * Dn / 4,  TPB), TPB>>>(wo_w, wop, Dn * Dn);

    cudaFuncSetAttribute(gemm_pairs_kernel,
                         cudaFuncAttributeMaxDynamicSharedMemorySize, GEMM_SMEM);

    // Merged QKV projection + fused RoPE (rope on cols < Dn+KVD = Q and K)
    gemm_pairs_kernel<<<dim3(NQKV / 128, Mn / 128), TPB, GEMM_SMEM>>>(
        ap, wqkvp, wq_b, wk_b, wv_b, q_p, k_p, v_p, Dn, Dn + KVD, fcos, fsin);

    // Flash attention (tensor cores)
    cudaFuncSetAttribute(attn_tc_kernel, cudaFuncAttributeMaxDynamicSharedMemorySize,
                         ATTN_SMEM);
    attn_tc_kernel<<<dim3(Sn / 128, Hn, Bn), TPB, ATTN_SMEM>>>();

    // O projection: pack attn (reuse ap), GEMM into d_out (no rope, no bias)
    pack_hilo_kernel<<<cdiv(Mn * Dn / 4, TPB), TPB>>>(attn_p, ap, Mn * Dn);
    gemm_pairs_kernel<<<dim3(Dn / 128, Mn / 128), TPB, GEMM_SMEM>>>(
        ap, wop, nullptr, nullptr, nullptr, out, out, out, Dn, 0, fcos, fsin);
}

// round 10
// speedup vs baseline: 1.0847x; 1.0042x over previous
// R9: fused multi-tensor pack kernel (MLP=4) + attention epilogue writes hi/lo pairs
// directly (g_attn and post-attn pack eliminated). GEMM (R6/R8) and attention (R5)
// mainloops unchanged. Label: "pack-fuse-mlp4".
#include <cuda_runtime.h>
#include <cuda_bf16.h>
#include <cstdint>

// Problem constants (Qwen2 GQA): B=2, S=2048, D=3584, H=28, KV=4, HD=128
#define Bn    2
#define Sn    2048
#define Dn    3584
#define Hn    28
#define KVn   4
#define HDn   128
#define NREP  7
#define Mn    (Bn * Sn)          // 4096
#define KVD   (KVn * HDn)        // 512
#define NQKV  (Dn + 2 * KVD)     // 4608
#define SCALE 0.08838834764831845f

// fp32 scratch
__device__ float g_q[(size_t)Mn * Dn];
__device__ float g_k[(size_t)Mn * KVD];
__device__ float g_v[(size_t)Mn * KVD];
// planar (hi,lo) bf16 pair arrays
__device__ __nv_bfloat162 g_ap   [(size_t)Mn   * Dn];   // x pairs, later attn pairs
__device__ __nv_bfloat162 g_wqkvp[(size_t)NQKV * Dn];   // wq|wk|wv stacked rows
__device__ __nv_bfloat162 g_wop  [(size_t)Dn   * Dn];

// ===========================================================================
// mma/ldsm helpers
// ===========================================================================
__device__ __forceinline__ void ldsm4(uint32_t& r0, uint32_t& r1,
                                      uint32_t& r2, uint32_t& r3, uint32_t addr)
{
    asm volatile("ldmatrix.sync.aligned.m8n8.x4.shared.b16 {%0,%1,%2,%3}, [%4];\n"
                 : "=r"(r0), "=r"(r1), "=r"(r2), "=r"(r3) : "r"(addr));
}

__device__ __forceinline__ void ldsm4t(uint32_t& r0, uint32_t& r1,
                                       uint32_t& r2, uint32_t& r3, uint32_t addr)
{
    asm volatile("ldmatrix.sync.aligned.m8n8.x4.trans.shared.b16 {%0,%1,%2,%3}, [%4];\n"
                 : "=r"(r0), "=r"(r1), "=r"(r2), "=r"(r3) : "r"(addr));
}

__device__ __forceinline__ void mma16816(float* c, const uint32_t* a,
                                         uint32_t b0, uint32_t b1)
{
    asm volatile(
        "mma.sync.aligned.m16n8k16.row.col.f32.bf16.bf16.f32 "
        "{%0,%1,%2,%3}, {%4,%5,%6,%7}, {%8,%9}, {%0,%1,%2,%3};\n"
        : "+f"(c[0]), "+f"(c[1]), "+f"(c[2]), "+f"(c[3])
        : "r"(a[0]), "r"(a[1]), "r"(a[2]), "r"(a[3]), "r"(b0), "r"(b1));
}

// ===========================================================================
// Fused pack: all 5 fp32 tensors -> (hi,lo) pair arrays in ONE launch.
// 16 elems/thread, 4 independent float4 loads in flight (MLP=4).
// Region boundaries (elements), all divisible by 16.
// ===========================================================================
#define PR0 ((size_t)Mn * Dn)
#define PR1 (PR0 + (size_t)Dn * Dn)
#define PR2 (PR1 + (size_t)KVD * Dn)
#define PR3 (PR2 + (size_t)KVD * Dn)
#define PR4 (PR3 + (size_t)Dn * Dn)
#define PACK_BLOCKS ((int)(PR4 / 16 / 256))   // 10752 (exact)

__global__ void pack_all_kernel(
    const float* __restrict__ x,  const float* __restrict__ wq,
    const float* __restrict__ wk, const float* __restrict__ wv,
    const float* __restrict__ wo)
{
    size_t base = ((size_t)blockIdx.x * blockDim.x + threadIdx.x) << 4;
    if (base >= PR4) return;

    const float* in;  __nv_bfloat162* out;  size_t off;
    if (base < PR0)      { in = x;  out = g_ap;                               off = base; }
    else if (base < PR1) { in = wq; out = g_wqkvp;                            off = base - PR0; }
    else if (base < PR2) { in = wk; out = g_wqkvp + (size_t)Dn * Dn;          off = base - PR1; }
    else if (base < PR3) { in = wv; out = g_wqkvp + (size_t)(Dn + KVD) * Dn;  off = base - PR2; }
    else                 { in = wo; out = g_wop;                              off = base - PR3; }

    float4 f[4];
#pragma unroll
    for (int j = 0; j < 4; ++j)
        f[j] = *(const float4*)(in + off + j * 4);   // 4 independent loads in flight

#pragma unroll
    for (int j = 0; j < 4; ++j) {
        float ff[4] = {f[j].x, f[j].y, f[j].z, f[j].w};
        __nv_bfloat162 o[4];
#pragma unroll
        for (int i = 0; i < 4; ++i) {
            __nv_bfloat16 hi = __float2bfloat16(ff[i]);
            __nv_bfloat16 lo = __float2bfloat16(ff[i] - __bfloat162float(hi));
            o[i].x = hi; o[i].y = lo;
        }
        *(uint4*)(out + off + j * 4) = *(const uint4*)o;
    }
}

// ===========================================================================
// Pair-fed bf16-split3 GEMM with region-dispatch epilogue + optional RoPE
// (mainloop/epilogue unchanged from R8, verified).
// ===========================================================================
#define LDA 56
#define OPST (128 * LDA)
#define GEMM_SMEM (4 * OPST * 2)   // 57344 bytes

template <int AMODE>
__device__ __forceinline__ void sts_trip(__nv_bfloat16* dst, uint4 p0, uint4 p1)
{
    uint32_t pw[8] = {p0.x, p0.y, p0.z, p0.w, p1.x, p1.y, p1.z, p1.w};
    __nv_bfloat16 t[24];
#pragma unroll
    for (int i = 0; i < 8; ++i) {
        __nv_bfloat162 pr = *(__nv_bfloat162*)&pw[i];
        if (AMODE) { t[3*i] = pr.x; t[3*i+1] = pr.x; t[3*i+2] = pr.y; }
        else       { t[3*i] = pr.x; t[3*i+1] = pr.y; t[3*i+2] = pr.x; }
    }
    uint2*       d = (uint2*)dst;
    const uint2* s = (const uint2*)t;
#pragma unroll
    for (int j = 0; j < 6; ++j) d[j] = s[j];
}

__global__ void __launch_bounds__(256) gemm_pairs_kernel(
    const __nv_bfloat162* __restrict__ A, const __nv_bfloat162* __restrict__ W,
    const float* __restrict__ bq, const float* __restrict__ bk,
    const float* __restrict__ bv,
    float* __restrict__ qd, float* __restrict__ kd, float* __restrict__ vd,
    int K, int rope_n,
    const float* __restrict__ cosT, const float* __restrict__ sinT)
{
    extern __shared__ __align__(16) __nv_bfloat16 smg[];
    __nv_bfloat16* As0 = smg;
    __nv_bfloat16* Ws0 = smg + OPST;

    const int tid  = threadIdx.x;
    const int lane = tid & 31, wid = tid >> 5;
    const int m0 = blockIdx.y << 7, n0 = blockIdx.x << 7;
    const int wm = (wid & 3) << 5;
    const int wn = (wid >> 2) << 6;

    const int pr = tid >> 1;
    const int pc = (tid & 1) << 3;
    const __nv_bfloat162* Ag = A + (size_t)(m0 + pr) * K + pc;
    const __nv_bfloat162* Wg = W + (size_t)(n0 + pr) * K + pc;
    const int soff = pr * LDA + pc * 3;

    const int a_row  = wm + (lane & 15);
    const int a_coff = (lane >> 4) << 3;
    const int b_row  = wn + ((lane >> 4) << 3) + (lane & 7);
    const int b_coff = ((lane >> 3) & 1) << 3;
    const uint32_t s_base = (uint32_t)__cvta_generic_to_shared(smg);

    float acc[2][8][4];
#pragma unroll
    for (int i = 0; i < 2; ++i)
#pragma unroll
        for (int j = 0; j < 8; ++j)
#pragma unroll
            for (int e = 0; e < 4; ++e) acc[i][j][e] = 0.f;

    uint4 ra0 = *(const uint4*)(Ag),     ra1 = *(const uint4*)(Ag + 4);
    uint4 rw0 = *(const uint4*)(Wg),     rw1 = *(const uint4*)(Wg + 4);
    sts_trip<1>(As0 + soff, ra0, ra1);
    sts_trip<0>(Ws0 + soff, rw0, rw1);
    if (16 < K) {
        ra0 = *(const uint4*)(Ag + 16);  ra1 = *(const uint4*)(Ag + 20);
        rw0 = *(const uint4*)(Wg + 16);  rw1 = *(const uint4*)(Wg + 20);
    }

    int cur = 0;
    for (int k0 = 0; k0 < K; k0 += 16) {
        __syncthreads();

        if (k0 + 16 < K) {
            const int nst = (cur ^ 1) * 2 * OPST;
            sts_trip<1>(smg + nst + soff, ra0, ra1);
            sts_trip<0>(smg + nst + OPST + soff, rw0, rw1);
            if (k0 + 32 < K) {
                ra0 = *(const uint4*)(Ag + k0 + 32);
                ra1 = *(const uint4*)(Ag + k0 + 36);
                rw0 = *(const uint4*)(Wg + k0 + 32);
                rw1 = *(const uint4*)(Wg + k0 + 36);
            }
        }

        const uint32_t as_b = s_base + (uint32_t)(cur * 2 * OPST * 2);
        const uint32_t ws_b = as_b + (uint32_t)(OPST * 2);
#pragma unroll
        for (int ks = 0; ks < 3; ++ks) {
            const int kk = ks << 4;
            uint32_t afr[2][4];
#pragma unroll
            for (int mi = 0; mi < 2; ++mi)
                ldsm4(afr[mi][0], afr[mi][1], afr[mi][2], afr[mi][3],
                      as_b + (uint32_t)(((a_row + mi * 16) * LDA + kk + a_coff) * 2));
            uint32_t bfr[4][4];
#pragma unroll
            for (int nq = 0; nq < 4; ++nq)
                ldsm4(bfr[nq][0], bfr[nq][1], bfr[nq][2], bfr[nq][3],
                      ws_b + (uint32_t)(((b_row + nq * 16) * LDA + kk + b_coff) * 2));
#pragma unroll
            for (int mi = 0; mi < 2; ++mi)
#pragma unroll
                for (int nq = 0; nq < 4; ++nq) {
                    mma16816(acc[mi][nq * 2 + 0], afr[mi], bfr[nq][0], bfr[nq][1]);
                    mma16816(acc[mi][nq * 2 + 1], afr[mi], bfr[nq][2], bfr[nq][3]);
                }
        }
        cur ^= 1;
    }

    // ---- epilogue: region dispatch + bias + optional RoPE ----
    const int g = lane >> 2, t = lane & 3;
#pragma unroll
    for (int mi = 0; mi < 2; ++mi) {
        const int row0 = m0 + wm + mi * 16 + g;
        const int row1 = row0 + 8;
        const int s0 = row0 & (Sn - 1);
        const int s1 = row1 & (Sn - 1);
#pragma unroll
        for (int ni = 0; ni < 8; ++ni) {
            const int col0 = n0 + wn + ni * 8 + t * 2;   // even
            float* dst; int ccol, stride;
            float bb0 = 0.f, bb1 = 0.f;
            if (col0 < Dn) {
                dst = qd; ccol = col0; stride = Dn;
                if (bq) { bb0 = bq[col0]; bb1 = bq[col0 + 1]; }
            } else if (col0 < Dn + KVD) {
                dst = kd; ccol = col0 - Dn; stride = KVD;
                bb0 = bk[ccol]; bb1 = bk[ccol + 1];
            } else {
                dst = vd; ccol = col0 - Dn - KVD; stride = KVD;
                bb0 = bv[ccol]; bb1 = bv[ccol + 1];
            }
            float2 v0 = {acc[mi][ni][0] + bb0, acc[mi][ni][1] + bb1};
            float2 v1 = {acc[mi][ni][2] + bb0, acc[mi][ni][3] + bb1};
            if (col0 < rope_n) {
                const int p = (col0 & 127) >> 1;
                float c0 = cosT[s0 * 64 + p], sn0 = sinT[s0 * 64 + p];
                float c1 = cosT[s1 * 64 + p], sn1 = sinT[s1 * 64 + p];
                float2 r0 = {v0.x * c0 - v0.y * sn0, v0.x * sn0 + v0.y * c0};
                float2 r1 = {v1.x * c1 - v1.y * sn1, v1.x * sn1 + v1.y * c1};
                v0 = r0; v1 = r1;
            }
            *(float2*)(dst + (size_t)row0 * stride + ccol) = v0;
            *(float2*)(dst + (size_t)row1 * stride + ccol) = v1;
        }
    }
}

// ===========================================================================
// Tensor-core flash attention (R5 mainloop; epilogue writes (hi,lo) pairs
// directly into g_ap — bit-identical to packing the old fp32 intermediate).
// ===========================================================================
#define LQA 136
#define LPV 72
#define ATTN_SMEM ((2 * 128 * LQA + 4 * 64 * LQA + 2 * 128 * LPV) * 2)

__device__ __forceinline__ void cvt4hl(__nv_bfloat16* dhi, __nv_bfloat16* dlo, float4 v)
{
    float f[4] = {v.x, v.y, v.z, v.w};
    __nv_bfloat16 h[4], l[4];
#pragma unroll
    for (int i = 0; i < 4; ++i) {
        h[i] = __float2bfloat16(f[i]);
        l[i] = __float2bfloat16(f[i] - __bfloat162float(h[i]));
    }
    *(uint2*)dhi = *(const uint2*)h;
    *(uint2*)dlo = *(const uint2*)l;
}

__device__ __forceinline__ __nv_bfloat162 hl_pair(float v)
{
    __nv_bfloat162 p;
    p.x = __float2bfloat16(v);
    p.y = __float2bfloat16(v - __bfloat162float(p.x));
    return p;
}

__global__ void __launch_bounds__(256) attn_tc_kernel()
{
    extern __shared__ __align__(16) __nv_bfloat16 smb[];
    __nv_bfloat16* Qhi = smb;
    __nv_bfloat16* Qlo = Qhi + 128 * LQA;
    __nv_bfloat16* Khi = Qlo + 128 * LQA;
    __nv_bfloat16* Klo = Khi + 64 * LQA;
    __nv_bfloat16* Vhi = Klo + 64 * LQA;
    __nv_bfloat16* Vlo = Vhi + 64 * LQA;
    __nv_bfloat16* Phi = Vlo + 64 * LQA;
    __nv_bfloat16* Plo = Phi + 128 * LPV;

    const int qt = blockIdx.x, h = blockIdx.y, b = blockIdx.z;
    const int kvh = h / NREP;
    const int tid = threadIdx.x;
    const int lane = tid & 31, w = tid >> 5;
    const int qi0 = qt << 7;

    {
        const float* qg = g_q + (size_t)(b * Sn + qi0) * Dn + h * HDn;
        int r = tid >> 1, c0 = (tid & 1) << 6;
#pragma unroll
        for (int c = 0; c < 64; c += 4) {
            float4 v = *(const float4*)(qg + (size_t)r * Dn + c0 + c);
            cvt4hl(Qhi + r * LQA + c0 + c, Qlo + r * LQA + c0 + c, v);
        }
    }

    const int a_row_l = lane & 15;
    const int a_coff  = (lane >> 4) << 3;
    const int b_row_l = ((lane >> 4) << 3) + (lane & 7);
    const int b_coff  = ((lane >> 3) & 1) << 3;
    const int t_row = (((lane >> 3) & 1) << 3) + (lane & 7);
    const int t_col = (lane >> 4) << 3;

    const uint32_t qhi_b = (uint32_t)__cvta_generic_to_shared(Qhi);
    const uint32_t qlo_b = (uint32_t)__cvta_generic_to_shared(Qlo);
    const uint32_t khi_b = (uint32_t)__cvta_generic_to_shared(Khi);
    const uint32_t klo_b = (uint32_t)__cvta_generic_to_shared(Klo);
    const uint32_t vhi_b = (uint32_t)__cvta_generic_to_shared(Vhi);
    const uint32_t vlo_b = (uint32_t)__cvta_generic_to_shared(Vlo);
    const uint32_t phi_b = (uint32_t)__cvta_generic_to_shared(Phi);
    const uint32_t plo_b = (uint32_t)__cvta_generic_to_shared(Plo);

    const int g  = lane >> 2;
    const int t4 = lane & 3;
    const int qglob0 = qi0 + w * 16 + g;
    const int qglob1 = qglob0 + 8;

    float oacc[16][4];
#pragma unroll
    for (int i = 0; i < 16; ++i)
#pragma unroll
        for (int e = 0; e < 4; ++e) oacc[i][e] = 0.f;
    float m0 = -1e30f, m1 = -1e30f, l0 = 0.f, l1 = 0.f;

    const float* kg_base = g_k + (size_t)(b * Sn) * KVD + kvh * HDn;
    const float* vg_base = g_v + (size_t)(b * Sn) * KVD + kvh * HDn;

    const int jmax = qi0 + 64;
    for (int j0 = 0; j0 <= jmax; j0 += 64) {
        __syncthreads();
        {
            int r = tid >> 2, c0 = (tid & 3) << 5;
            const float* kg = kg_base + (size_t)(j0 + r) * KVD + c0;
            const float* vg = vg_base + (size_t)(j0 + r) * KVD + c0;
#pragma unroll
            for (int c = 0; c < 32; c += 4) {
                cvt4hl(Khi + r * LQA + c0 + c, Klo + r * LQA + c0 + c,
                       *(const float4*)(kg + c));
                cvt4hl(Vhi + r * LQA + c0 + c, Vlo + r * LQA + c0 + c,
                       *(const float4*)(vg + c));
            }
        }
        __syncthreads();

        float sacc[8][4];
#pragma unroll
        for (int i = 0; i < 8; ++i)
#pragma unroll
            for (int e = 0; e < 4; ++e) sacc[i][e] = 0.f;

#pragma unroll
        for (int pass = 0; pass < 3; ++pass) {
            const uint32_t ab = (pass == 2) ? qlo_b : qhi_b;
            const uint32_t bb = (pass == 1) ? klo_b : khi_b;
#pragma unroll
            for (int ks = 0; ks < 8; ++ks) {
                const int kk = ks << 4;
                uint32_t afr[4];
                ldsm4(afr[0], afr[1], afr[2], afr[3],
                      ab + (uint32_t)(((w * 16 + a_row_l) * LQA + kk + a_coff) * 2));
                uint32_t bfr[4][4];
#pragma unroll
                for (int nq = 0; nq < 4; ++nq)
                    ldsm4(bfr[nq][0], bfr[nq][1], bfr[nq][2], bfr[nq][3],
                          bb + (uint32_t)(((nq * 16 + b_row_l) * LQA + kk + b_coff) * 2));
#pragma unroll
                for (int nq = 0; nq < 4; ++nq) {
                    mma16816(sacc[nq * 2 + 0], afr, bfr[nq][0], bfr[nq][1]);
                    mma16816(sacc[nq * 2 + 1], afr, bfr[nq][2], bfr[nq][3]);
                }
            }
        }

#pragma unroll
        for (int nq = 0; nq < 8; ++nq) {
            int cb = j0 + nq * 8 + t4 * 2;
            float s0 = sacc[nq][0] * SCALE;
            float s1 = sacc[nq][1] * SCALE;
            float s2 = sacc[nq][2] * SCALE;
            float s3 = sacc[nq][3] * SCALE;
            if (cb     > qglob0) s0 = -1e30f;
            if (cb + 1 > qglob0) s1 = -1e30f;
            if (cb     > qglob1) s2 = -1e30f;
            if (cb + 1 > qglob1) s3 = -1e30f;
            sacc[nq][0] = s0; sacc[nq][1] = s1;
            sacc[nq][2] = s2; sacc[nq][3] = s3;
        }

        float rm0 = -1e30f, rm1 = -1e30f;
#pragma unroll
        for (int nq = 0; nq < 8; ++nq) {
            rm0 = fmaxf(rm0, fmaxf(sacc[nq][0], sacc[nq][1]));
            rm1 = fmaxf(rm1, fmaxf(sacc[nq][2], sacc[nq][3]));
        }
        rm0 = fmaxf(rm0, __shfl_xor_sync(0xffffffffu, rm0, 1));
        rm0 = fmaxf(rm0, __shfl_xor_sync(0xffffffffu, rm0, 2));
        rm1 = fmaxf(rm1, __shfl_xor_sync(0xffffffffu, rm1, 1));
        rm1 = fmaxf(rm1, __shfl_xor_sync(0xffffffffu, rm1, 2));
        float mn0 = fmaxf(m0, rm0), mn1 = fmaxf(m1, rm1);
        float al0 = __expf(m0 - mn0), al1 = __expf(m1 - mn1);

        __syncwarp();
        float rs0 = 0.f, rs1 = 0.f;
        const int prow0 = w * 16 + g;
#pragma unroll
        for (int nq = 0; nq < 8; ++nq) {
            int col = nq * 8 + t4 * 2;
            float p0 = __expf(sacc[nq][0] - mn0);
            float p1 = __expf(sacc[nq][1] - mn0);
            float p2 = __expf(sacc[nq][2] - mn1);
            float p3 = __expf(sacc[nq][3] - mn1);
            rs0 += p0 + p1;  rs1 += p2 + p3;
            __nv_bfloat162 h01, l01, h23, l23;
            h01.x = __float2bfloat16(p0);
            h01.y = __float2bfloat16(p1);
            l01.x = __float2bfloat16(p0 - __bfloat162float(h01.x));
            l01.y = __float2bfloat16(p1 - __bfloat162float(h01.y));
            h23.x = __float2bfloat16(p2);
            h23.y = __float2bfloat16(p3);
            l23.x = __float2bfloat16(p2 - __bfloat162float(h23.x));
            l23.y = __float2bfloat16(p3 - __bfloat162float(h23.y));
            *(__nv_bfloat162*)(Phi + prow0 * LPV + col)       = h01;
            *(__nv_bfloat162*)(Plo + prow0 * LPV + col)       = l01;
            *(__nv_bfloat162*)(Phi + (prow0 + 8) * LPV + col) = h23;
            *(__nv_bfloat162*)(Plo + (prow0 + 8) * LPV + col) = l23;
        }
        rs0 += __shfl_xor_sync(0xffffffffu, rs0, 1);
        rs0 += __shfl_xor_sync(0xffffffffu, rs0, 2);
        rs1 += __shfl_xor_sync(0xffffffffu, rs1, 1);
        rs1 += __shfl_xor_sync(0xffffffffu, rs1, 2);
        l0 = l0 * al0 + rs0;  l1 = l1 * al1 + rs1;
        m0 = mn0;  m1 = mn1;
#pragma unroll
        for (int nn = 0; nn < 16; ++nn) {
            oacc[nn][0] *= al0; oacc[nn][1] *= al0;
            oacc[nn][2] *= al1; oacc[nn][3] *= al1;
        }
        __syncwarp();

#pragma unroll
        for (int pass = 0; pass < 3; ++pass) {
            const uint32_t ab = (pass == 2) ? plo_b : phi_b;
            const uint32_t bb = (pass == 1) ? vlo_b : vhi_b;
#pragma unroll
            for (int ks = 0; ks < 4; ++ks) {
                const int kk = ks << 4;
                uint32_t afr[4];
                ldsm4(afr[0], afr[1], afr[2], afr[3],
                      ab + (uint32_t)(((w * 16 + a_row_l) * LPV + kk + a_coff) * 2));
#pragma unroll
                for (int nh = 0; nh < 8; ++nh) {
                    uint32_t b0, b1, b2, b3;
                    ldsm4t(b0, b1, b2, b3,
                           bb + (uint32_t)(((kk + t_row) * LQA + nh * 16 + t_col) * 2));
                    mma16816(oacc[nh * 2 + 0], afr, b0, b1);
                    mma16816(oacc[nh * 2 + 1], afr, b2, b3);
                }
            }
        }
    }

    // epilogue: normalize and write (hi,lo) pairs directly into g_ap
    float inv0 = 1.f / l0, inv1 = 1.f / l1;
    __nv_bfloat162* ob0 = g_ap + (size_t)(b * Sn + qglob0) * Dn + h * HDn;
    __nv_bfloat162* ob1 = g_ap + (size_t)(b * Sn + qglob1) * Dn + h * HDn;
#pragma unroll
    for (int nn = 0; nn < 16; ++nn) {
        int col = nn * 8 + t4 * 2;
        __nv_bfloat162 p00 = hl_pair(oacc[nn][0] * inv0);
        __nv_bfloat162 p01 = hl_pair(oacc[nn][1] * inv0);
        __nv_bfloat162 p10 = hl_pair(oacc[nn][2] * inv1);
        __nv_bfloat162 p11 = hl_pair(oacc[nn][3] * inv1);
        uint2 s0, s1;
        s0.x = *(uint32_t*)&p00;  s0.y = *(uint32_t*)&p01;
        s1.x = *(uint32_t*)&p10;  s1.y = *(uint32_t*)&p11;
        *(uint2*)(ob0 + col) = s0;
        *(uint2*)(ob1 + col) = s1;
    }
}

// ===========================================================================
// Launch
// ===========================================================================
extern "C" void kernel_launch(void* const* d_in, const int* in_sizes, int n_in,
                              void* d_out, int out_size)
{
    const float* x    = (const float*)d_in[0];
    const float* wq_w = (const float*)d_in[1];
    const float* wq_b = (const float*)d_in[2];
    const float* wk_w = (const float*)d_in[3];
    const float* wk_b = (const float*)d_in[4];
    const float* wv_w = (const float*)d_in[5];
    const float* wv_b = (const float*)d_in[6];
    const float* wo_w = (const float*)d_in[7];
    const float* fcos = (const float*)d_in[10];
    const float* fsin = (const float*)d_in[11];
    float* out = (float*)d_out;

    float *q_p, *k_p, *v_p;
    __nv_bfloat162 *ap, *wqkvp, *wop;
    cudaGetSymbolAddress((void**)&q_p, g_q);
    cudaGetSymbolAddress((void**)&k_p, g_k);
    cudaGetSymbolAddress((void**)&v_p, g_v);
    cudaGetSymbolAddress((void**)&ap,    g_ap);
    cudaGetSymbolAddress((void**)&wqkvp, g_wqkvp);
    cudaGetSymbolAddress((void**)&wop,   g_wop);

    const int TPB = 256;

    // Fused pack: all 5 tensors in one launch (MLP=4)
    pack_all_kernel<<<PACK_BLOCKS, TPB>>>(x, wq_w, wk_w, wv_w, wo_w);

    cudaFuncSetAttribute(gemm_pairs_kernel,
                         cudaFuncAttributeMaxDynamicSharedMemorySize, GEMM_SMEM);

    // Merged QKV projection + fused RoPE
    gemm_pairs_kernel<<<dim3(NQKV / 128, Mn / 128), TPB, GEMM_SMEM>>>(
        ap, wqkvp, wq_b, wk_b, wv_b, q_p, k_p, v_p, Dn, Dn + KVD, fcos, fsin);

    // Flash attention (writes hi/lo pairs straight into g_ap)
    cudaFuncSetAttribute(attn_tc_kernel, cudaFuncAttributeMaxDynamicSharedMemorySize,
                         ATTN_SMEM);
    attn_tc_kernel<<<dim3(Sn / 128, Hn, Bn), TPB, ATTN_SMEM>>>();

    // O projection straight into d_out (no rope, no bias)
    gemm_pairs_kernel<<<dim3(Dn / 128, Mn / 128), TPB, GEMM_SMEM>>>(
        ap, wop, nullptr, nullptr, nullptr, out, out, out, Dn, 0, fcos, fsin);
}

// round 11
// speedup vs baseline: 1.2407x; 1.1438x over previous
// R10: planar hi/lo smem GEMM with register-level fragment reuse (1.5x less
// smem traffic per mma; GEMM was measured L1=85%/tensor=44% smem-bound).
// Pack/attention unchanged from R9. Label: "gemm-planar-fragreuse".
#include <cuda_runtime.h>
#include <cuda_bf16.h>
#include <cstdint>

// Problem constants (Qwen2 GQA): B=2, S=2048, D=3584, H=28, KV=4, HD=128
#define Bn    2
#define Sn    2048
#define Dn    3584
#define Hn    28
#define KVn   4
#define HDn   128
#define NREP  7
#define Mn    (Bn * Sn)          // 4096
#define KVD   (KVn * HDn)        // 512
#define NQKV  (Dn + 2 * KVD)     // 4608
#define SCALE 0.08838834764831845f

// fp32 scratch
__device__ float g_q[(size_t)Mn * Dn];
__device__ float g_k[(size_t)Mn * KVD];
__device__ float g_v[(size_t)Mn * KVD];
// planar (hi,lo) bf16 pair arrays
__device__ __nv_bfloat162 g_ap   [(size_t)Mn   * Dn];   // x pairs, later attn pairs
__device__ __nv_bfloat162 g_wqkvp[(size_t)NQKV * Dn];   // wq|wk|wv stacked rows
__device__ __nv_bfloat162 g_wop  [(size_t)Dn   * Dn];

// ===========================================================================
// mma/ldsm helpers
// ===========================================================================
__device__ __forceinline__ void ldsm4(uint32_t& r0, uint32_t& r1,
                                      uint32_t& r2, uint32_t& r3, uint32_t addr)
{
    asm volatile("ldmatrix.sync.aligned.m8n8.x4.shared.b16 {%0,%1,%2,%3}, [%4];\n"
                 : "=r"(r0), "=r"(r1), "=r"(r2), "=r"(r3) : "r"(addr));
}

__device__ __forceinline__ void ldsm4t(uint32_t& r0, uint32_t& r1,
                                       uint32_t& r2, uint32_t& r3, uint32_t addr)
{
    asm volatile("ldmatrix.sync.aligned.m8n8.x4.trans.shared.b16 {%0,%1,%2,%3}, [%4];\n"
                 : "=r"(r0), "=r"(r1), "=r"(r2), "=r"(r3) : "r"(addr));
}

__device__ __forceinline__ void mma16816(float* c, const uint32_t* a,
                                         uint32_t b0, uint32_t b1)
{
    asm volatile(
        "mma.sync.aligned.m16n8k16.row.col.f32.bf16.bf16.f32 "
        "{%0,%1,%2,%3}, {%4,%5,%6,%7}, {%8,%9}, {%0,%1,%2,%3};\n"
        : "+f"(c[0]), "+f"(c[1]), "+f"(c[2]), "+f"(c[3])
        : "r"(a[0]), "r"(a[1]), "r"(a[2]), "r"(a[3]), "r"(b0), "r"(b1));
}

// ===========================================================================
// Fused pack (unchanged from R9)
// ===========================================================================
#define PR0 ((size_t)Mn * Dn)
#define PR1 (PR0 + (size_t)Dn * Dn)
#define PR2 (PR1 + (size_t)KVD * Dn)
#define PR3 (PR2 + (size_t)KVD * Dn)
#define PR4 (PR3 + (size_t)Dn * Dn)
#define PACK_BLOCKS ((int)(PR4 / 16 / 256))

__global__ void pack_all_kernel(
    const float* __restrict__ x,  const float* __restrict__ wq,
    const float* __restrict__ wk, const float* __restrict__ wv,
    const float* __restrict__ wo)
{
    size_t base = ((size_t)blockIdx.x * blockDim.x + threadIdx.x) << 4;
    if (base >= PR4) return;

    const float* in;  __nv_bfloat162* out;  size_t off;
    if (base < PR0)      { in = x;  out = g_ap;                               off = base; }
    else if (base < PR1) { in = wq; out = g_wqkvp;                            off = base - PR0; }
    else if (base < PR2) { in = wk; out = g_wqkvp + (size_t)Dn * Dn;          off = base - PR1; }
    else if (base < PR3) { in = wv; out = g_wqkvp + (size_t)(Dn + KVD) * Dn;  off = base - PR2; }
    else                 { in = wo; out = g_wop;                              off = base - PR3; }

    float4 f[4];
#pragma unroll
    for (int j = 0; j < 4; ++j)
        f[j] = *(const float4*)(in + off + j * 4);

#pragma unroll
    for (int j = 0; j < 4; ++j) {
        float ff[4] = {f[j].x, f[j].y, f[j].z, f[j].w};
        __nv_bfloat162 o[4];
#pragma unroll
        for (int i = 0; i < 4; ++i) {
            __nv_bfloat16 hi = __float2bfloat16(ff[i]);
            __nv_bfloat16 lo = __float2bfloat16(ff[i] - __bfloat162float(hi));
            o[i].x = hi; o[i].y = lo;
        }
        *(uint4*)(out + off + j * 4) = *(const uint4*)o;
    }
}

// ===========================================================================
// Planar bf16-split3 GEMM: C[M,N] = A*W^T (+bias), fp32 out.
// smem per stage: 4 planes (Ahi, Alo, Whi, Wlo), each 128 rows x 16 bf16,
// row stride 24 bf16 (48 B: 16B-aligned, 3r mod 8 -> LDSM conflict-free).
// Per K-16 step: 4 A-ldsm4 (hi+lo, reused) + per nq {Bhi ldsm4 -> hh + lh mma,
// Blo ldsm4 -> hl mma}. 12 ldsm4 / 48 mma (was 18/48); STS 4 B/elem (was 6).
// Double-buffer, one barrier per K-step. Epilogue: region dispatch + RoPE.
// ===========================================================================
#define LDP 24                         // plane row stride (bf16)
#define PLANE (128 * LDP)              // 3072 bf16 = 6144 B
#define STAGE_E (4 * PLANE)            // bf16 elems per stage
#define GEMM_SMEM (2 * STAGE_E * 2)    // 49152 bytes

// split 8 (hi,lo) pairs (two uint4) into hi/lo planes (two uint2 each)
__device__ __forceinline__ void split_store(__nv_bfloat16* hip, __nv_bfloat16* lop,
                                            uint4 p0, uint4 p1)
{
    uint2 h0, l0, h1, l1;
    h0.x = (p0.x & 0xFFFFu) | (p0.y << 16);
    h0.y = (p0.z & 0xFFFFu) | (p0.w << 16);
    l0.x = (p0.x >> 16)     | (p0.y & 0xFFFF0000u);
    l0.y = (p0.z >> 16)     | (p0.w & 0xFFFF0000u);
    h1.x = (p1.x & 0xFFFFu) | (p1.y << 16);
    h1.y = (p1.z & 0xFFFFu) | (p1.w << 16);
    l1.x = (p1.x >> 16)     | (p1.y & 0xFFFF0000u);
    l1.y = (p1.z >> 16)     | (p1.w & 0xFFFF0000u);
    *(uint2*)hip       = h0;  *(uint2*)(hip + 4) = h1;
    *(uint2*)lop       = l0;  *(uint2*)(lop + 4) = l1;
}

__global__ void __launch_bounds__(256, 2) gemm_pairs_kernel(
    const __nv_bfloat162* __restrict__ A, const __nv_bfloat162* __restrict__ W,
    const float* __restrict__ bq, const float* __restrict__ bk,
    const float* __restrict__ bv,
    float* __restrict__ qd, float* __restrict__ kd, float* __restrict__ vd,
    int K, int rope_n,
    const float* __restrict__ cosT, const float* __restrict__ sinT)
{
    extern __shared__ __align__(16) __nv_bfloat16 smg[];

    const int tid  = threadIdx.x;
    const int lane = tid & 31, wid = tid >> 5;
    const int m0 = blockIdx.y << 7, n0 = blockIdx.x << 7;
    const int wm = (wid & 3) << 5;
    const int wn = (wid >> 2) << 6;

    // producer mapping: row 0..127, fp32-col offset 0 or 8
    const int pr = tid >> 1;
    const int pc = (tid & 1) << 3;
    const __nv_bfloat162* Ag = A + (size_t)(m0 + pr) * K + pc;
    const __nv_bfloat162* Wg = W + (size_t)(n0 + pr) * K + pc;
    const int soff = pr * LDP + pc;     // elem offset within a plane

    // ldsm lane->address components (validated mapping; single k16 per step)
    const int a_row  = wm + (lane & 15);
    const int a_coff = (lane >> 4) << 3;          // 0 or 8 (bf16 cols)
    const int b_row  = wn + ((lane >> 4) << 3) + (lane & 7);
    const int b_coff = ((lane >> 3) & 1) << 3;
    const uint32_t s_base = (uint32_t)__cvta_generic_to_shared(smg);

    float acc[2][8][4];
#pragma unroll
    for (int i = 0; i < 2; ++i)
#pragma unroll
        for (int j = 0; j < 8; ++j)
#pragma unroll
            for (int e = 0; e < 4; ++e) acc[i][j][e] = 0.f;

    // prologue: tile 0 -> stage 0; prefetch tile 1 into regs
    uint4 ra0 = *(const uint4*)(Ag),     ra1 = *(const uint4*)(Ag + 4);
    uint4 rw0 = *(const uint4*)(Wg),     rw1 = *(const uint4*)(Wg + 4);
    split_store(smg + soff,             smg + PLANE + soff,     ra0, ra1);  // Ahi/Alo
    split_store(smg + 2 * PLANE + soff, smg + 3 * PLANE + soff, rw0, rw1);  // Whi/Wlo
    if (16 < K) {
        ra0 = *(const uint4*)(Ag + 16);  ra1 = *(const uint4*)(Ag + 20);
        rw0 = *(const uint4*)(Wg + 16);  rw1 = *(const uint4*)(Wg + 20);
    }

    int cur = 0;
    for (int k0 = 0; k0 < K; k0 += 16) {
        __syncthreads();   // stores to stage[cur] visible; reads of stage[cur^1] done

        if (k0 + 16 < K) {
            __nv_bfloat16* nst = smg + (cur ^ 1) * STAGE_E;
            split_store(nst + soff,             nst + PLANE + soff,     ra0, ra1);
            split_store(nst + 2 * PLANE + soff, nst + 3 * PLANE + soff, rw0, rw1);
            if (k0 + 32 < K) {
                ra0 = *(const uint4*)(Ag + k0 + 32);
                ra1 = *(const uint4*)(Ag + k0 + 36);
                rw0 = *(const uint4*)(Wg + k0 + 32);
                rw1 = *(const uint4*)(Wg + k0 + 36);
            }
        }

        const uint32_t st  = s_base + (uint32_t)(cur * STAGE_E * 2);
        const uint32_t ahi = st;
        const uint32_t alo = st + PLANE * 2;
        const uint32_t whi = st + 2 * PLANE * 2;
        const uint32_t wlo = st + 3 * PLANE * 2;

        // A fragments once per step (hi and lo), reused across all N
        uint32_t Ah[2][4], Al[2][4];
#pragma unroll
        for (int mi = 0; mi < 2; ++mi) {
            const uint32_t roff = (uint32_t)(((a_row + mi * 16) * LDP + a_coff) * 2);
            ldsm4(Ah[mi][0], Ah[mi][1], Ah[mi][2], Ah[mi][3], ahi + roff);
            ldsm4(Al[mi][0], Al[mi][1], Al[mi][2], Al[mi][3], alo + roff);
        }

#pragma unroll
        for (int nq = 0; nq < 4; ++nq) {
            const uint32_t broff = (uint32_t)(((nq * 16 + b_row) * LDP + b_coff) * 2);
            uint32_t Bh[4];
            ldsm4(Bh[0], Bh[1], Bh[2], Bh[3], whi + broff);
#pragma unroll
            for (int mi = 0; mi < 2; ++mi) {
                mma16816(acc[mi][nq * 2 + 0], Ah[mi], Bh[0], Bh[1]);   // hi*hi
                mma16816(acc[mi][nq * 2 + 1], Ah[mi], Bh[2], Bh[3]);
            }
#pragma unroll
            for (int mi = 0; mi < 2; ++mi) {
                mma16816(acc[mi][nq * 2 + 0], Al[mi], Bh[0], Bh[1]);   // lo*hi
                mma16816(acc[mi][nq * 2 + 1], Al[mi], Bh[2], Bh[3]);
            }
            uint32_t Bl[4];
            ldsm4(Bl[0], Bl[1], Bl[2], Bl[3], wlo + broff);
#pragma unroll
            for (int mi = 0; mi < 2; ++mi) {
                mma16816(acc[mi][nq * 2 + 0], Ah[mi], Bl[0], Bl[1]);   // hi*lo
                mma16816(acc[mi][nq * 2 + 1], Ah[mi], Bl[2], Bl[3]);
            }
        }
        cur ^= 1;
    }

    // ---- epilogue: region dispatch + bias + optional RoPE (unchanged) ----
    const int g = lane >> 2, t = lane & 3;
#pragma unroll
    for (int mi = 0; mi < 2; ++mi) {
        const int row0 = m0 + wm + mi * 16 + g;
        const int row1 = row0 + 8;
        const int s0 = row0 & (Sn - 1);
        const int s1 = row1 & (Sn - 1);
#pragma unroll
        for (int ni = 0; ni < 8; ++ni) {
            const int col0 = n0 + wn + ni * 8 + t * 2;   // even
            float* dst; int ccol, stride;
            float bb0 = 0.f, bb1 = 0.f;
            if (col0 < Dn) {
                dst = qd; ccol = col0; stride = Dn;
                if (bq) { bb0 = bq[col0]; bb1 = bq[col0 + 1]; }
            } else if (col0 < Dn + KVD) {
                dst = kd; ccol = col0 - Dn; stride = KVD;
                bb0 = bk[ccol]; bb1 = bk[ccol + 1];
            } else {
                dst = vd; ccol = col0 - Dn - KVD; stride = KVD;
                bb0 = bv[ccol]; bb1 = bv[ccol + 1];
            }
            float2 v0 = {acc[mi][ni][0] + bb0, acc[mi][ni][1] + bb1};
            float2 v1 = {acc[mi][ni][2] + bb0, acc[mi][ni][3] + bb1};
            if (col0 < rope_n) {
                const int p = (col0 & 127) >> 1;
                float c0 = cosT[s0 * 64 + p], sn0 = sinT[s0 * 64 + p];
                float c1 = cosT[s1 * 64 + p], sn1 = sinT[s1 * 64 + p];
                float2 r0 = {v0.x * c0 - v0.y * sn0, v0.x * sn0 + v0.y * c0};
                float2 r1 = {v1.x * c1 - v1.y * sn1, v1.x * sn1 + v1.y * c1};
                v0 = r0; v1 = r1;
            }
            *(float2*)(dst + (size_t)row0 * stride + ccol) = v0;
            *(float2*)(dst + (size_t)row1 * stride + ccol) = v1;
        }
    }
}

// ===========================================================================
// Tensor-core flash attention (unchanged from R9)
// ===========================================================================
#define LQA 136
#define LPV 72
#define ATTN_SMEM ((2 * 128 * LQA + 4 * 64 * LQA + 2 * 128 * LPV) * 2)

__device__ __forceinline__ void cvt4hl(__nv_bfloat16* dhi, __nv_bfloat16* dlo, float4 v)
{
    float f[4] = {v.x, v.y, v.z, v.w};
    __nv_bfloat16 h[4], l[4];
#pragma unroll
    for (int i = 0; i < 4; ++i) {
        h[i] = __float2bfloat16(f[i]);
        l[i] = __float2bfloat16(f[i] - __bfloat162float(h[i]));
    }
    *(uint2*)dhi = *(const uint2*)h;
    *(uint2*)dlo = *(const uint2*)l;
}

__device__ __forceinline__ __nv_bfloat162 hl_pair(float v)
{
    __nv_bfloat162 p;
    p.x = __float2bfloat16(v);
    p.y = __float2bfloat16(v - __bfloat162float(p.x));
    return p;
}

__global__ void __launch_bounds__(256) attn_tc_kernel()
{
    extern __shared__ __align__(16) __nv_bfloat16 smb[];
    __nv_bfloat16* Qhi = smb;
    __nv_bfloat16* Qlo = Qhi + 128 * LQA;
    __nv_bfloat16* Khi = Qlo + 128 * LQA;
    __nv_bfloat16* Klo = Khi + 64 * LQA;
    __nv_bfloat16* Vhi = Klo + 64 * LQA;
    __nv_bfloat16* Vlo = Vhi + 64 * LQA;
    __nv_bfloat16* Phi = Vlo + 64 * LQA;
    __nv_bfloat16* Plo = Phi + 128 * LPV;

    const int qt = blockIdx.x, h = blockIdx.y, b = blockIdx.z;
    const int kvh = h / NREP;
    const int tid = threadIdx.x;
    const int lane = tid & 31, w = tid >> 5;
    const int qi0 = qt << 7;

    {
        const float* qg = g_q + (size_t)(b * Sn + qi0) * Dn + h * HDn;
        int r = tid >> 1, c0 = (tid & 1) << 6;
#pragma unroll
        for (int c = 0; c < 64; c += 4) {
            float4 v = *(const float4*)(qg + (size_t)r * Dn + c0 + c);
            cvt4hl(Qhi + r * LQA + c0 + c, Qlo + r * LQA + c0 + c, v);
        }
    }

    const int a_row_l = lane & 15;
    const int a_coff  = (lane >> 4) << 3;
    const int b_row_l = ((lane >> 4) << 3) + (lane & 7);
    const int b_coff  = ((lane >> 3) & 1) << 3;
    const int t_row = (((lane >> 3) & 1) << 3) + (lane & 7);
    const int t_col = (lane >> 4) << 3;

    const uint32_t qhi_b = (uint32_t)__cvta_generic_to_shared(Qhi);
    const uint32_t qlo_b = (uint32_t)__cvta_generic_to_shared(Qlo);
    const uint32_t khi_b = (uint32_t)__cvta_generic_to_shared(Khi);
    const uint32_t klo_b = (uint32_t)__cvta_generic_to_shared(Klo);
    const uint32_t vhi_b = (uint32_t)__cvta_generic_to_shared(Vhi);
    const uint32_t vlo_b = (uint32_t)__cvta_generic_to_shared(Vlo);
    const uint32_t phi_b = (uint32_t)__cvta_generic_to_shared(Phi);
    const uint32_t plo_b = (uint32_t)__cvta_generic_to_shared(Plo);

    const int g  = lane >> 2;
    const int t4 = lane & 3;
    const int qglob0 = qi0 + w * 16 + g;
    const int qglob1 = qglob0 + 8;

    float oacc[16][4];
#pragma unroll
    for (int i = 0; i < 16; ++i)
#pragma unroll
        for (int e = 0; e < 4; ++e) oacc[i][e] = 0.f;
    float m0 = -1e30f, m1 = -1e30f, l0 = 0.f, l1 = 0.f;

    const float* kg_base = g_k + (size_t)(b * Sn) * KVD + kvh * HDn;
    const float* vg_base = g_v + (size_t)(b * Sn) * KVD + kvh * HDn;

    const int jmax = qi0 + 64;
    for (int j0 = 0; j0 <= jmax; j0 += 64) {
        __syncthreads();
        {
            int r = tid >> 2, c0 = (tid & 3) << 5;
            const float* kg = kg_base + (size_t)(j0 + r) * KVD + c0;
            const float* vg = vg_base + (size_t)(j0 + r) * KVD + c0;
#pragma unroll
            for (int c = 0; c < 32; c += 4) {
                cvt4hl(Khi + r * LQA + c0 + c, Klo + r * LQA + c0 + c,
                       *(const float4*)(kg + c));
                cvt4hl(Vhi + r * LQA + c0 + c, Vlo + r * LQA + c0 + c,
                       *(const float4*)(vg + c));
            }
        }
        __syncthreads();

        float sacc[8][4];
#pragma unroll
        for (int i = 0; i < 8; ++i)
#pragma unroll
            for (int e = 0; e < 4; ++e) sacc[i][e] = 0.f;

#pragma unroll
        for (int pass = 0; pass < 3; ++pass) {
            const uint32_t ab = (pass == 2) ? qlo_b : qhi_b;
            const uint32_t bb = (pass == 1) ? klo_b : khi_b;
#pragma unroll
            for (int ks = 0; ks < 8; ++ks) {
                const int kk = ks << 4;
                uint32_t afr[4];
                ldsm4(afr[0], afr[1], afr[2], afr[3],
                      ab + (uint32_t)(((w * 16 + a_row_l) * LQA + kk + a_coff) * 2));
                uint32_t bfr[4][4];
#pragma unroll
                for (int nq = 0; nq < 4; ++nq)
                    ldsm4(bfr[nq][0], bfr[nq][1], bfr[nq][2], bfr[nq][3],
                          bb + (uint32_t)(((nq * 16 + b_row_l) * LQA + kk + b_coff) * 2));
#pragma unroll
                for (int nq = 0; nq < 4; ++nq) {
                    mma16816(sacc[nq * 2 + 0], afr, bfr[nq][0], bfr[nq][1]);
                    mma16816(sacc[nq * 2 + 1], afr, bfr[nq][2], bfr[nq][3]);
                }
            }
        }

#pragma unroll
        for (int nq = 0; nq < 8; ++nq) {
            int cb = j0 + nq * 8 + t4 * 2;
            float s0 = sacc[nq][0] * SCALE;
            float s1 = sacc[nq][1] * SCALE;
            float s2 = sacc[nq][2] * SCALE;
            float s3 = sacc[nq][3] * SCALE;
            if (cb     > qglob0) s0 = -1e30f;
            if (cb + 1 > qglob0) s1 = -1e30f;
            if (cb     > qglob1) s2 = -1e30f;
            if (cb + 1 > qglob1) s3 = -1e30f;
            sacc[nq][0] = s0; sacc[nq][1] = s1;
            sacc[nq][2] = s2; sacc[nq][3] = s3;
        }

        float rm0 = -1e30f, rm1 = -1e30f;
#pragma unroll
        for (int nq = 0; nq < 8; ++nq) {
            rm0 = fmaxf(rm0, fmaxf(sacc[nq][0], sacc[nq][1]));
            rm1 = fmaxf(rm1, fmaxf(sacc[nq][2], sacc[nq][3]));
        }
        rm0 = fmaxf(rm0, __shfl_xor_sync(0xffffffffu, rm0, 1));
        rm0 = fmaxf(rm0, __shfl_xor_sync(0xffffffffu, rm0, 2));
        rm1 = fmaxf(rm1, __shfl_xor_sync(0xffffffffu, rm1, 1));
        rm1 = fmaxf(rm1, __shfl_xor_sync(0xffffffffu, rm1, 2));
        float mn0 = fmaxf(m0, rm0), mn1 = fmaxf(m1, rm1);
        float al0 = __expf(m0 - mn0), al1 = __expf(m1 - mn1);

        __syncwarp();
        float rs0 = 0.f, rs1 = 0.f;
        const int prow0 = w * 16 + g;
#pragma unroll
        for (int nq = 0; nq < 8; ++nq) {
            int col = nq * 8 + t4 * 2;
            float p0 = __expf(sacc[nq][0] - mn0);
            float p1 = __expf(sacc[nq][1] - mn0);
            float p2 = __expf(sacc[nq][2] - mn1);
            float p3 = __expf(sacc[nq][3] - mn1);
            rs0 += p0 + p1;  rs1 += p2 + p3;
            __nv_bfloat162 h01, l01, h23, l23;
            h01.x = __float2bfloat16(p0);
            h01.y = __float2bfloat16(p1);
            l01.x = __float2bfloat16(p0 - __bfloat162float(h01.x));
            l01.y = __float2bfloat16(p1 - __bfloat162float(h01.y));
            h23.x = __float2bfloat16(p2);
            h23.y = __float2bfloat16(p3);
            l23.x = __float2bfloat16(p2 - __bfloat162float(h23.x));
            l23.y = __float2bfloat16(p3 - __bfloat162float(h23.y));
            *(__nv_bfloat162*)(Phi + prow0 * LPV + col)       = h01;
            *(__nv_bfloat162*)(Plo + prow0 * LPV + col)       = l01;
            *(__nv_bfloat162*)(Phi + (prow0 + 8) * LPV + col) = h23;
            *(__nv_bfloat162*)(Plo + (prow0 + 8) * LPV + col) = l23;
        }
        rs0 += __shfl_xor_sync(0xffffffffu, rs0, 1);
        rs0 += __shfl_xor_sync(0xffffffffu, rs0, 2);
        rs1 += __shfl_xor_sync(0xffffffffu, rs1, 1);
        rs1 += __shfl_xor_sync(0xffffffffu, rs1, 2);
        l0 = l0 * al0 + rs0;  l1 = l1 * al1 + rs1;
        m0 = mn0;  m1 = mn1;
#pragma unroll
        for (int nn = 0; nn < 16; ++nn) {
            oacc[nn][0] *= al0; oacc[nn][1] *= al0;
            oacc[nn][2] *= al1; oacc[nn][3] *= al1;
        }
        __syncwarp();

#pragma unroll
        for (int pass = 0; pass < 3; ++pass) {
            const uint32_t ab = (pass == 2) ? plo_b : phi_b;
            const uint32_t bb = (pass == 1) ? vlo_b : vhi_b;
#pragma unroll
            for (int ks = 0; ks < 4; ++ks) {
                const int kk = ks << 4;
                uint32_t afr[4];
                ldsm4(afr[0], afr[1], afr[2], afr[3],
                      ab + (uint32_t)(((w * 16 + a_row_l) * LPV + kk + a_coff) * 2));
#pragma unroll
                for (int nh = 0; nh < 8; ++nh) {
                    uint32_t b0, b1, b2, b3;
                    ldsm4t(b0, b1, b2, b3,
                           bb + (uint32_t)(((kk + t_row) * LQA + nh * 16 + t_col) * 2));
                    mma16816(oacc[nh * 2 + 0], afr, b0, b1);
                    mma16816(oacc[nh * 2 + 1], afr, b2, b3);
                }
            }
        }
    }

    float inv0 = 1.f / l0, inv1 = 1.f / l1;
    __nv_bfloat162* ob0 = g_ap + (size_t)(b * Sn + qglob0) * Dn + h * HDn;
    __nv_bfloat162* ob1 = g_ap + (size_t)(b * Sn + qglob1) * Dn + h * HDn;
#pragma unroll
    for (int nn = 0; nn < 16; ++nn) {
        int col = nn * 8 + t4 * 2;
        __nv_bfloat162 p00 = hl_pair(oacc[nn][0] * inv0);
        __nv_bfloat162 p01 = hl_pair(oacc[nn][1] * inv0);
        __nv_bfloat162 p10 = hl_pair(oacc[nn][2] * inv1);
        __nv_bfloat162 p11 = hl_pair(oacc[nn][3] * inv1);
        uint2 s0, s1;
        s0.x = *(uint32_t*)&p00;  s0.y = *(uint32_t*)&p01;
        s1.x = *(uint32_t*)&p10;  s1.y = *(uint32_t*)&p11;
        *(uint2*)(ob0 + col) = s0;
        *(uint2*)(ob1 + col) = s1;
    }
}

// ===========================================================================
// Launch
// ===========================================================================
extern "C" void kernel_launch(void* const* d_in, const int* in_sizes, int n_in,
                              void* d_out, int out_size)
{
    const float* x    = (const float*)d_in[0];
    const float* wq_w = (const float*)d_in[1];
    const float* wq_b = (const float*)d_in[2];
    const float* wk_w = (const float*)d_in[3];
    const float* wk_b = (const float*)d_in[4];
    const float* wv_w = (const float*)d_in[5];
    const float* wv_b = (const float*)d_in[6];
    const float* wo_w = (const float*)d_in[7];
    const float* fcos = (const float*)d_in[10];
    const float* fsin = (const float*)d_in[11];
    float* out = (float*)d_out;

    float *q_p, *k_p, *v_p;
    __nv_bfloat162 *ap, *wqkvp, *wop;
    cudaGetSymbolAddress((void**)&q_p, g_q);
    cudaGetSymbolAddress((void**)&k_p, g_k);
    cudaGetSymbolAddress((void**)&v_p, g_v);
    cudaGetSymbolAddress((void**)&ap,    g_ap);
    cudaGetSymbolAddress((void**)&wqkvp, g_wqkvp);
    cudaGetSymbolAddress((void**)&wop,   g_wop);

    const int TPB = 256;

    // Fused pack: all 5 tensors in one launch
    pack_all_kernel<<<PACK_BLOCKS, TPB>>>(x, wq_w, wk_w, wv_w, wo_w);

    cudaFuncSetAttribute(gemm_pairs_kernel,
                         cudaFuncAttributeMaxDynamicSharedMemorySize, GEMM_SMEM);

    // Merged QKV projection + fused RoPE
    gemm_pairs_kernel<<<dim3(NQKV / 128, Mn / 128), TPB, GEMM_SMEM>>>(
        ap, wqkvp, wq_b, wk_b, wv_b, q_p, k_p, v_p, Dn, Dn + KVD, fcos, fsin);

    // Flash attention (writes hi/lo pairs straight into g_ap)
    cudaFuncSetAttribute(attn_tc_kernel, cudaFuncAttributeMaxDynamicSharedMemorySize,
                         ATTN_SMEM);
    attn_tc_kernel<<<dim3(Sn / 128, Hn, Bn), TPB, ATTN_SMEM>>>();

    // O projection straight into d_out (no rope, no bias)
    gemm_pairs_kernel<<<dim3(Dn / 128, Mn / 128), TPB, GEMM_SMEM>>>(
        ap, wop, nullptr, nullptr, nullptr, out, out, out, Dn, 0, fcos, fsin);
}